// round 11
// baseline (speedup 1.0000x reference)
#include <cuda_runtime.h>
#include <math.h>
#include <float.h>

#define NPTS 8192
#define KNN  20

// ------------------------- scratch (__device__ globals, no allocation) ------
__device__ float g_D[(size_t)NPTS * NPTS];   // 256 MB dist matrix
__device__ float g_x2[NPTS];
__device__ int   g_idx[NPTS * KNN];
__device__ float g_cat[NPTS * 420];          // x1|x2|x3 concatenated (60|120|240)
__device__ float g_h1[NPTS * 1024];
__device__ float g_h2[NPTS * 256];
__device__ float g_h3[NPTS * 128];

// ------------------------- squared norms ------------------------------------
// Frozen arithmetic recipe (matches reference bit-for-bit on ranking path):
//   C small (3)    : one thread per row, sequential separately-rounded adds.
//   C large (60/120): one warp per row; lane-strided accumulate then
//                    full-warp shuffle-DOWN tree (offsets 16,8,4,2,1).
__global__ void sqnorm_seq_kernel(const float* __restrict__ X, int ld, int C,
                                  float* __restrict__ x2) {
    int i = blockIdx.x * blockDim.x + threadIdx.x;
    if (i >= NPTS) return;
    const float* r = X + (size_t)i * ld;
    float s = 0.f;
    for (int c = 0; c < C; ++c)
        s = __fadd_rn(s, __fmul_rn(r[c], r[c]));
    x2[i] = s;
}

__global__ void sqnorm_warp_kernel(const float* __restrict__ X, int ld, int C,
                                   float* __restrict__ x2) {
    const int lane = threadIdx.x & 31;
    const int row  = (blockIdx.x * blockDim.x + threadIdx.x) >> 5;
    if (row >= NPTS) return;

    const float* r = X + (size_t)row * ld;
    float s = 0.f;
    for (int c = lane; c < C; c += 32)
        s = __fadd_rn(s, __fmul_rn(r[c], r[c]));
#pragma unroll
    for (int off = 16; off > 0; off >>= 1)
        s = __fadd_rn(s, __shfl_down_sync(0xffffffffu, s, off));
    if (lane == 0) x2[row] = s;
}

#define BM 128
#define BN 128
#define BK 16

// triangle decode: linear block id -> (bx, by), by <= bx
__device__ __forceinline__ void tri_decode(int t, int& bx, int& by) {
    bx = (int)((sqrtf(8.f * (float)t + 1.f) - 1.f) * 0.5f);
    while ((bx + 1) * (bx + 2) / 2 <= t) ++bx;
    while (bx * (bx + 1) / 2 > t) --bx;
    by = t - bx * (bx + 1) / 2;
}

// epilogue + symmetric dual store shared by the dist kernels
__device__ __forceinline__ void dist_store(float acc[8][8],
                                           const float* __restrict__ x2v,
                                           float* __restrict__ D,
                                           int i0, int j0, int tx, int ty,
                                           bool offdiag) {
    float res[8][8];
#pragma unroll
    for (int u = 0; u < 8; ++u) {
        int i = i0 + ty * 8 + u;
#pragma unroll
        for (int v = 0; v < 8; ++v) {
            int j = j0 + tx * 8 + v;
            float s = __fadd_rn(x2v[i], x2v[j]);
            res[u][v] = __fsub_rn(s, __fmul_rn(2.f, acc[u][v]));
        }
    }
#pragma unroll
    for (int u = 0; u < 8; ++u) {
        int i = i0 + ty * 8 + u;
        *(float4*)&D[(size_t)i * NPTS + j0 + tx * 8]     = *(float4*)&res[u][0];
        *(float4*)&D[(size_t)i * NPTS + j0 + tx * 8 + 4] = *(float4*)&res[u][4];
    }
    if (offdiag) {
#pragma unroll
        for (int v = 0; v < 8; ++v) {
            int j = j0 + tx * 8 + v;
            float4 p0 = make_float4(res[0][v], res[1][v], res[2][v], res[3][v]);
            float4 p1 = make_float4(res[4][v], res[5][v], res[6][v], res[7][v]);
            *(float4*)&D[(size_t)j * NPTS + i0 + ty * 8]     = p0;
            *(float4*)&D[(size_t)j * NPTS + i0 + ty * 8 + 4] = p1;
        }
    }
}

// ------------------------- K=3 specialized symmetric distance ---------------
__global__ __launch_bounds__(256) void dist3_kernel(
    const float* __restrict__ X,
    const float* __restrict__ x2v,
    float* __restrict__ D) {
    __shared__ float A3[3][BM + 4];
    __shared__ float B3[3][BN + 4];

    int bx, by;
    tri_decode(blockIdx.x, bx, by);
    const int i0 = bx * BM, j0 = by * BN;
    const int tid = threadIdx.x;
    const int tx = tid & 15, ty = tid >> 4;

    if (tid < 128) {
        const float* ra = X + (size_t)(i0 + tid) * 3;
        const float* rb = X + (size_t)(j0 + tid) * 3;
#pragma unroll
        for (int c = 0; c < 3; ++c) { A3[c][tid] = ra[c]; B3[c][tid] = rb[c]; }
    }
    __syncthreads();

    float acc[8][8];
#pragma unroll
    for (int u = 0; u < 8; ++u)
#pragma unroll
        for (int v = 0; v < 8; ++v) acc[u][v] = 0.f;

#pragma unroll
    for (int k = 0; k < 3; ++k) {
        float a[8], b[8];
        *(float4*)&a[0] = *(const float4*)&A3[k][ty * 8];
        *(float4*)&a[4] = *(const float4*)&A3[k][ty * 8 + 4];
        *(float4*)&b[0] = *(const float4*)&B3[k][tx * 8];
        *(float4*)&b[4] = *(const float4*)&B3[k][tx * 8 + 4];
#pragma unroll
        for (int u = 0; u < 8; ++u)
#pragma unroll
            for (int v = 0; v < 8; ++v)
                acc[u][v] = fmaf(a[u], b[v], acc[u][v]);
    }

    dist_store(acc, x2v, D, i0, j0, tx, ty, bx != by);
}

// ------------------------- full-K smem-resident symmetric distance ----------
// K (60 or 120) fits entirely in shared memory: load both 128-row K-panels
// once, ONE barrier, then a single uninterrupted ascending-k FFMA loop of
// exactly K steps (bitwise identical to the padded multi-tile chain: removed
// steps were exact fma(0,0,acc) no-ops). No prefetch machinery, no
// intermediate syncs, no zero-padding work.
template <int K>
__global__ __launch_bounds__(256, 1) void distK_kernel(
    const float* __restrict__ X, int ld,
    const float* __restrict__ x2v,
    float* __restrict__ D) {
    extern __shared__ float smext[];
    float (*As)[BM + 4] = (float(*)[BM + 4])smext;
    float (*Bs)[BN + 4] = (float(*)[BN + 4])(smext + K * (BM + 4));

    int bx, by;
    tri_decode(blockIdx.x, bx, by);
    const int i0 = bx * BM, j0 = by * BN;
    const int tid = threadIdx.x;
    const int tx = tid & 15, ty = tid >> 4;

    // load full K-panels (compile-time K -> cheap div/mod)
    for (int e = tid; e < BM * K; e += 256) {
        int r = e / K, c = e - r * K;
        As[c][r] = X[(size_t)(i0 + r) * ld + c];
        Bs[c][r] = X[(size_t)(j0 + r) * ld + c];
    }
    __syncthreads();

    float acc[8][8];
#pragma unroll
    for (int u = 0; u < 8; ++u)
#pragma unroll
        for (int v = 0; v < 8; ++v) acc[u][v] = 0.f;

#pragma unroll 4
    for (int k = 0; k < K; ++k) {
        float a[8], b[8];
        *(float4*)&a[0] = *(const float4*)&As[k][ty * 8];
        *(float4*)&a[4] = *(const float4*)&As[k][ty * 8 + 4];
        *(float4*)&b[0] = *(const float4*)&Bs[k][tx * 8];
        *(float4*)&b[4] = *(const float4*)&Bs[k][tx * 8 + 4];
#pragma unroll
        for (int u = 0; u < 8; ++u)
#pragma unroll
            for (int v = 0; v < 8; ++v)
                acc[u][v] = fmaf(a[u], b[v], acc[u][v]);
    }

    dist_store(acc, x2v, D, i0, j0, tx, ty, bx != by);
}

// ------------------------- tiled fp32 GEMM (MLP, double-buffered) -----------
// C[i,j] = relu(dot(A_i, W[:,j]) + bias[j]),  W row-major [K,N].
__global__ __launch_bounds__(256, 2) void gemm_kernel(
    const float* __restrict__ A, int lda,
    const float* __restrict__ B, int ldb,
    const float* __restrict__ bias,
    float* __restrict__ Cout, int ldc,
    int N, int K) {
    __shared__ float As[2][BK][BM + 4];
    __shared__ float Bs[2][BK][BN + 4];

    const int tid = threadIdx.x;
    const int tx = tid & 15, ty = tid >> 4;
    const int i0 = blockIdx.y * BM;
    const int j0 = blockIdx.x * BN;

    float acc[8][8];
#pragma unroll
    for (int u = 0; u < 8; ++u)
#pragma unroll
        for (int v = 0; v < 8; ++v) acc[u][v] = 0.f;

#pragma unroll
    for (int p = 0; p < 8; ++p) {
        int e = tid + 256 * p;
        {
            int r = e >> 4, c = e & 15;
            As[0][c][r] = (c < K) ? A[(size_t)(i0 + r) * lda + c] : 0.f;
        }
        {
            int r = e >> 7, c = e & 127;
            Bs[0][r][c] = (r < K && j0 + c < N)
                              ? B[(size_t)r * ldb + j0 + c] : 0.f;
        }
    }
    __syncthreads();

    const int nt = (K + BK - 1) / BK;
    int buf = 0;
    for (int t = 1; t < nt; ++t) {
        const int kk = t * BK;
        float pa[8], pb[8];
#pragma unroll
        for (int p = 0; p < 8; ++p) {
            int e = tid + 256 * p;
            {
                int r = e >> 4, c = e & 15;
                pa[p] = (kk + c < K) ? A[(size_t)(i0 + r) * lda + kk + c] : 0.f;
            }
            {
                int r = e >> 7, c = e & 127;
                pb[p] = (kk + r < K && j0 + c < N)
                            ? B[(size_t)(kk + r) * ldb + j0 + c] : 0.f;
            }
        }
#pragma unroll
        for (int k = 0; k < BK; ++k) {
            float a[8], b[8];
            *(float4*)&a[0] = *(const float4*)&As[buf][k][ty * 8];
            *(float4*)&a[4] = *(const float4*)&As[buf][k][ty * 8 + 4];
            *(float4*)&b[0] = *(const float4*)&Bs[buf][k][tx * 8];
            *(float4*)&b[4] = *(const float4*)&Bs[buf][k][tx * 8 + 4];
#pragma unroll
            for (int u = 0; u < 8; ++u)
#pragma unroll
                for (int v = 0; v < 8; ++v)
                    acc[u][v] = fmaf(a[u], b[v], acc[u][v]);
        }
#pragma unroll
        for (int p = 0; p < 8; ++p) {
            int e = tid + 256 * p;
            { int r = e >> 4, c = e & 15;  As[buf ^ 1][c][r] = pa[p]; }
            { int r = e >> 7, c = e & 127; Bs[buf ^ 1][r][c] = pb[p]; }
        }
        __syncthreads();
        buf ^= 1;
    }
#pragma unroll
    for (int k = 0; k < BK; ++k) {
        float a[8], b[8];
        *(float4*)&a[0] = *(const float4*)&As[buf][k][ty * 8];
        *(float4*)&a[4] = *(const float4*)&As[buf][k][ty * 8 + 4];
        *(float4*)&b[0] = *(const float4*)&Bs[buf][k][tx * 8];
        *(float4*)&b[4] = *(const float4*)&Bs[buf][k][tx * 8 + 4];
#pragma unroll
        for (int u = 0; u < 8; ++u)
#pragma unroll
            for (int v = 0; v < 8; ++v)
                acc[u][v] = fmaf(a[u], b[v], acc[u][v]);
    }

#pragma unroll
    for (int u = 0; u < 8; ++u) {
        int i = i0 + ty * 8 + u;
#pragma unroll
        for (int v = 0; v < 8; ++v) {
            int j = j0 + tx * 8 + v;
            if (j < N)
                Cout[(size_t)i * ldc + j] =
                    fmaxf(__fadd_rn(acc[u][v], bias[j]), 0.f);
        }
    }
}

// ------------------------- top-20 selection (warp per row) ------------------
__global__ void topk_kernel(const float* __restrict__ D, int* __restrict__ out) {
    __shared__ float sd[8][KNN];
    __shared__ int   si[8][KNN];

    const int lane = threadIdx.x & 31;
    const int wloc = threadIdx.x >> 5;
    const int row  = (blockIdx.x * blockDim.x + threadIdx.x) >> 5;

    if (lane < KNN) { sd[wloc][lane] = FLT_MAX; si[wloc][lane] = 0x7fffffff; }
    __syncwarp();

    const float* r = D + (size_t)row * NPTS;
    float thresh = FLT_MAX;

    for (int base = 0; base < NPTS; base += 32) {
        float d = r[base + lane];
        unsigned m = __ballot_sync(0xffffffffu, d < thresh);
        while (m) {
            int src = __ffs(m) - 1;
            m &= m - 1;
            float dc = __shfl_sync(0xffffffffu, d, src);
            int   jc = base + src;
            if (lane == 0) {
                if (dc < sd[wloc][KNN - 1]) {
                    int p = KNN - 1;
                    while (p > 0 && sd[wloc][p - 1] > dc) {
                        sd[wloc][p] = sd[wloc][p - 1];
                        si[wloc][p] = si[wloc][p - 1];
                        --p;
                    }
                    sd[wloc][p] = dc;
                    si[wloc][p] = jc;
                }
            }
            __syncwarp();
            thresh = sd[wloc][KNN - 1];
        }
    }
    if (lane < KNN) out[row * KNN + lane] = si[wloc][lane];
}

// ------------------------- erosion EdgeConv ---------------------------------
__global__ void erode_kernel(const float* __restrict__ Xin, int ldin,
                             const int* __restrict__ idx,
                             const float* __restrict__ w,
                             float* __restrict__ out, int ldout,
                             int F, int C) {
    __shared__ float nb[KNN * 120];    // max C = 120
    const int i = blockIdx.x;
    const int* ip = idx + i * KNN;

    for (int e = threadIdx.x; e < KNN * C; e += blockDim.x) {
        int k = e / C, c = e - k * C;
        nb[e] = Xin[(size_t)ip[k] * ldin + c];
    }
    __syncthreads();

    for (int e = threadIdx.x; e < F * C; e += blockDim.x) {
        int f = e / C, c = e - f * C;
        float mn = FLT_MAX;
        const float* wf = w + (size_t)f * KNN * C + c;
#pragma unroll 4
        for (int k = 0; k < KNN; ++k)
            mn = fminf(mn, __fsub_rn(nb[k * C + c], wf[k * C]));
        out[(size_t)i * ldout + e] = mn;
    }
}

// ------------------------- final linear + log_softmax -----------------------
__global__ void head_kernel(const float* __restrict__ H,
                            const float* __restrict__ wo,
                            const float* __restrict__ bo,
                            float* __restrict__ out) {
    __shared__ float h[128];
    __shared__ float lg[40];
    __shared__ float s_lse;
    const int i = blockIdx.x;
    const int t = threadIdx.x;              // 128 threads

    h[t] = H[(size_t)i * 128 + t];
    __syncthreads();

    if (t < 40) {
        float s = 0.f;
#pragma unroll 8
        for (int k = 0; k < 128; ++k) s = fmaf(h[k], wo[k * 40 + t], s);
        lg[t] = __fadd_rn(s, bo[t]);
    }
    __syncthreads();

    if (t == 0) {
        float m = -FLT_MAX;
        for (int n = 0; n < 40; ++n) m = fmaxf(m, lg[n]);
        float s = 0.f;
        for (int n = 0; n < 40; ++n) s = __fadd_rn(s, expf(__fsub_rn(lg[n], m)));
        s_lse = __fadd_rn(m, logf(s));
    }
    __syncthreads();

    if (t < 40) out[(size_t)i * 40 + t] = __fsub_rn(lg[t], s_lse);
}

// ------------------------- launch sequence ----------------------------------
extern "C" void kernel_launch(void* const* d_in, const int* in_sizes, int n_in,
                              void* d_out, int out_size) {
    const float* x      = (const float*)d_in[0];
    const float* w1     = (const float*)d_in[1];
    const float* w2     = (const float*)d_in[2];
    const float* w3     = (const float*)d_in[3];
    const float* lin1_w = (const float*)d_in[4];
    const float* lin1_b = (const float*)d_in[5];
    const float* wa     = (const float*)d_in[6];
    const float* ba     = (const float*)d_in[7];
    const float* wb     = (const float*)d_in[8];
    const float* bb     = (const float*)d_in[9];
    const float* wo     = (const float*)d_in[10];
    const float* bo     = (const float*)d_in[11];
    float* out = (float*)d_out;

    float *D, *x2, *cat, *h1, *h2, *h3;
    int* idxp;
    cudaGetSymbolAddress((void**)&D,   g_D);
    cudaGetSymbolAddress((void**)&x2,  g_x2);
    cudaGetSymbolAddress((void**)&idxp,g_idx);
    cudaGetSymbolAddress((void**)&cat, g_cat);
    cudaGetSymbolAddress((void**)&h1,  g_h1);
    cudaGetSymbolAddress((void**)&h2,  g_h2);
    cudaGetSymbolAddress((void**)&h3,  g_h3);

    const int NB = NPTS / BM;                 // 64 tiles per dim
    const int NTRI = NB * (NB + 1) / 2;       // 2080 lower-triangle blocks

    const int smem60  = 2 * 60  * (BM + 4) * (int)sizeof(float);   // ~63 KB
    const int smem120 = 2 * 120 * (BM + 4) * (int)sizeof(float);   // ~127 KB
    cudaFuncSetAttribute(distK_kernel<60>,
                         cudaFuncAttributeMaxDynamicSharedMemorySize, smem60);
    cudaFuncSetAttribute(distK_kernel<120>,
                         cudaFuncAttributeMaxDynamicSharedMemorySize, smem120);

    // ---- layer 1: kNN on x (C=3), erode -> cat[:, 0:60]
    sqnorm_seq_kernel<<<32, 256>>>(x, 3, 3, x2);
    dist3_kernel<<<NTRI, 256>>>(x, x2, D);
    topk_kernel<<<NPTS / 8, 256>>>(D, idxp);
    erode_kernel<<<NPTS, 128>>>(x, 3, idxp, w1, cat, 420, 20, 3);

    // ---- layer 2: kNN on x1 (C=60), erode -> cat[:, 60:180]
    sqnorm_warp_kernel<<<NPTS / 8, 256>>>(cat, 420, 60, x2);
    distK_kernel<60><<<NTRI, 256, smem60>>>(cat, 420, x2, D);
    topk_kernel<<<NPTS / 8, 256>>>(D, idxp);
    erode_kernel<<<NPTS, 128>>>(cat, 420, idxp, w2, cat + 60, 420, 2, 60);

    // ---- layer 3: kNN on x2 (C=120), erode -> cat[:, 180:420]
    sqnorm_warp_kernel<<<NPTS / 8, 256>>>(cat + 60, 420, 120, x2);
    distK_kernel<120><<<NTRI, 256, smem120>>>(cat + 60, 420, x2, D);
    topk_kernel<<<NPTS / 8, 256>>>(D, idxp);
    erode_kernel<<<NPTS, 128>>>(cat + 60, 420, idxp, w3, cat + 180, 420, 2, 120);

    // ---- MLP head
    gemm_kernel<<<dim3(1024 / BN, NPTS / BM), 256>>>(
        cat, 420, lin1_w, 1024, lin1_b, h1, 1024, 1024, 420);
    gemm_kernel<<<dim3(2, NPTS / BM), 256>>>(
        h1, 1024, wa, 256, ba, h2, 256, 256, 1024);
    gemm_kernel<<<dim3(1, NPTS / BM), 256>>>(
        h2, 256, wb, 128, bb, h3, 128, 128, 256);

    head_kernel<<<NPTS, 128>>>(h3, wo, bo, out);
}

// round 12
// speedup vs baseline: 1.1016x; 1.1016x over previous
#include <cuda_runtime.h>
#include <math.h>
#include <float.h>

#define NPTS 8192
#define KNN  20

// ------------------------- scratch (__device__ globals, no allocation) ------
__device__ float g_D[(size_t)NPTS * NPTS];   // 256 MB dist matrix
__device__ float g_x2[NPTS];
__device__ int   g_idx[NPTS * KNN];
__device__ float g_cat[NPTS * 420];          // x1|x2|x3 concatenated (60|120|240)
__device__ float g_h1[NPTS * 1024];
__device__ float g_h2[NPTS * 256];
__device__ float g_h3[NPTS * 128];

// ------------------------- squared norms ------------------------------------
// Frozen arithmetic recipe (matches reference bit-for-bit on ranking path):
//   C small (3)    : one thread per row, sequential separately-rounded adds.
//   C large (60/120): one warp per row; lane-strided accumulate then
//                    full-warp shuffle-DOWN tree (offsets 16,8,4,2,1).
__global__ void sqnorm_seq_kernel(const float* __restrict__ X, int ld, int C,
                                  float* __restrict__ x2) {
    int i = blockIdx.x * blockDim.x + threadIdx.x;
    if (i >= NPTS) return;
    const float* r = X + (size_t)i * ld;
    float s = 0.f;
    for (int c = 0; c < C; ++c)
        s = __fadd_rn(s, __fmul_rn(r[c], r[c]));
    x2[i] = s;
}

__global__ void sqnorm_warp_kernel(const float* __restrict__ X, int ld, int C,
                                   float* __restrict__ x2) {
    const int lane = threadIdx.x & 31;
    const int row  = (blockIdx.x * blockDim.x + threadIdx.x) >> 5;
    if (row >= NPTS) return;

    const float* r = X + (size_t)row * ld;
    float s = 0.f;
    for (int c = lane; c < C; c += 32)
        s = __fadd_rn(s, __fmul_rn(r[c], r[c]));
#pragma unroll
    for (int off = 16; off > 0; off >>= 1)
        s = __fadd_rn(s, __shfl_down_sync(0xffffffffu, s, off));
    if (lane == 0) x2[row] = s;
}

#define BM 128
#define BN 128
#define BK 16

// triangle decode: linear block id -> (bx, by), by <= bx
__device__ __forceinline__ void tri_decode(int t, int& bx, int& by) {
    bx = (int)((sqrtf(8.f * (float)t + 1.f) - 1.f) * 0.5f);
    while ((bx + 1) * (bx + 2) / 2 <= t) ++bx;
    while (bx * (bx + 1) / 2 > t) --bx;
    by = t - bx * (bx + 1) / 2;
}

// epilogue + symmetric dual store shared by the dist kernels
__device__ __forceinline__ void dist_store(float acc[8][8],
                                           const float* __restrict__ x2v,
                                           float* __restrict__ D,
                                           int i0, int j0, int tx, int ty,
                                           bool offdiag) {
    float res[8][8];
#pragma unroll
    for (int u = 0; u < 8; ++u) {
        int i = i0 + ty * 8 + u;
#pragma unroll
        for (int v = 0; v < 8; ++v) {
            int j = j0 + tx * 8 + v;
            float s = __fadd_rn(x2v[i], x2v[j]);
            res[u][v] = __fsub_rn(s, __fmul_rn(2.f, acc[u][v]));
        }
    }
#pragma unroll
    for (int u = 0; u < 8; ++u) {
        int i = i0 + ty * 8 + u;
        *(float4*)&D[(size_t)i * NPTS + j0 + tx * 8]     = *(float4*)&res[u][0];
        *(float4*)&D[(size_t)i * NPTS + j0 + tx * 8 + 4] = *(float4*)&res[u][4];
    }
    if (offdiag) {
#pragma unroll
        for (int v = 0; v < 8; ++v) {
            int j = j0 + tx * 8 + v;
            float4 p0 = make_float4(res[0][v], res[1][v], res[2][v], res[3][v]);
            float4 p1 = make_float4(res[4][v], res[5][v], res[6][v], res[7][v]);
            *(float4*)&D[(size_t)j * NPTS + i0 + ty * 8]     = p0;
            *(float4*)&D[(size_t)j * NPTS + i0 + ty * 8 + 4] = p1;
        }
    }
}

// ------------------------- fused kNN for C=3 (no D matrix) ------------------
// Whole point set fits in smem (8192 x (3 coords + x2) = 128 KB). One warp
// per row; distances computed in registers with EXACTLY the dist3 chain:
//   acc = fmaf(a2,b2, fmaf(a1,b1, fmaf(a0,b0, 0)));
//   d   = fsub( fadd(x2i, x2j), fmul(2, acc) )
// and scanned in ascending j with strict '<' -- bitwise identical candidates
// and identical selection order vs the old dist3 + topk pair.
__global__ __launch_bounds__(1024, 1) void knn3_kernel(
    const float* __restrict__ X,
    const float* __restrict__ x2v,
    int* __restrict__ out) {
    extern __shared__ float sm[];
    float* A0 = sm;
    float* A1 = sm + NPTS;
    float* A2 = sm + 2 * NPTS;
    float* X2 = sm + 3 * NPTS;
    float* sd = X2 + NPTS;                     // [32][KNN]
    int*   si = (int*)(sd + 32 * KNN);         // [32][KNN]

    const int tid = threadIdx.x;
    for (int j = tid; j < NPTS; j += 1024) {
        const float* p = X + (size_t)j * 3;
        A0[j] = p[0]; A1[j] = p[1]; A2[j] = p[2];
        X2[j] = x2v[j];
    }
    __syncthreads();

    const int lane = tid & 31;
    const int w    = tid >> 5;                 // 32 warps
    const int row  = blockIdx.x * 32 + w;

    const float a0 = A0[row], a1 = A1[row], a2 = A2[row];
    const float xi = X2[row];

    float* wd = sd + w * KNN;
    int*   wi = si + w * KNN;
    if (lane < KNN) { wd[lane] = FLT_MAX; wi[lane] = 0x7fffffff; }
    __syncwarp();

    float thresh = FLT_MAX;
    for (int base = 0; base < NPTS; base += 32) {
        const int j = base + lane;
        float acc = fmaf(a0, A0[j], 0.f);
        acc = fmaf(a1, A1[j], acc);
        acc = fmaf(a2, A2[j], acc);
        float d = __fsub_rn(__fadd_rn(xi, X2[j]), __fmul_rn(2.f, acc));

        unsigned m = __ballot_sync(0xffffffffu, d < thresh);
        while (m) {
            int src = __ffs(m) - 1;
            m &= m - 1;
            float dc = __shfl_sync(0xffffffffu, d, src);
            int   jc = base + src;
            if (lane == 0) {
                if (dc < wd[KNN - 1]) {
                    int p = KNN - 1;
                    while (p > 0 && wd[p - 1] > dc) {
                        wd[p] = wd[p - 1];
                        wi[p] = wi[p - 1];
                        --p;
                    }
                    wd[p] = dc;
                    wi[p] = jc;
                }
            }
            __syncwarp();
            thresh = wd[KNN - 1];
        }
    }
    if (lane < KNN) out[row * KNN + lane] = wi[lane];
}

// ------------------------- symmetric pairwise distance (double-buffered) ----
// D[i,j] = (x2[i] + x2[j]) - 2*dot(X_i, X_j); lower-triangle blocks only,
// dual store. dot = ascending-k single-accumulator FFMA chain (unchanged).
__global__ __launch_bounds__(256, 2) void dist_sym_kernel(
    const float* __restrict__ X, int ld,
    const float* __restrict__ x2v,
    float* __restrict__ D, int K) {
    __shared__ float As[2][BK][BM + 4];
    __shared__ float Bs[2][BK][BN + 4];

    int bx, by;
    tri_decode(blockIdx.x, bx, by);
    const int i0 = bx * BM, j0 = by * BN;
    const int tid = threadIdx.x;
    const int tx = tid & 15, ty = tid >> 4;

    float acc[8][8];
#pragma unroll
    for (int u = 0; u < 8; ++u)
#pragma unroll
        for (int v = 0; v < 8; ++v) acc[u][v] = 0.f;

    // prologue: tile 0
#pragma unroll
    for (int p = 0; p < 8; ++p) {
        int e = tid + 256 * p, r = e >> 4, c = e & 15;
        As[0][c][r] = (c < K) ? X[(size_t)(i0 + r) * ld + c] : 0.f;
        Bs[0][c][r] = (c < K) ? X[(size_t)(j0 + r) * ld + c] : 0.f;
    }
    __syncthreads();

    const int nt = (K + BK - 1) / BK;
    int buf = 0;
    for (int t = 1; t < nt; ++t) {
        const int kk = t * BK;
        float pa[8], pb[8];
#pragma unroll
        for (int p = 0; p < 8; ++p) {
            int e = tid + 256 * p, r = e >> 4, c = e & 15;
            pa[p] = (kk + c < K) ? X[(size_t)(i0 + r) * ld + kk + c] : 0.f;
            pb[p] = (kk + c < K) ? X[(size_t)(j0 + r) * ld + kk + c] : 0.f;
        }
#pragma unroll
        for (int k = 0; k < BK; ++k) {
            float a[8], b[8];
            *(float4*)&a[0] = *(const float4*)&As[buf][k][ty * 8];
            *(float4*)&a[4] = *(const float4*)&As[buf][k][ty * 8 + 4];
            *(float4*)&b[0] = *(const float4*)&Bs[buf][k][tx * 8];
            *(float4*)&b[4] = *(const float4*)&Bs[buf][k][tx * 8 + 4];
#pragma unroll
            for (int u = 0; u < 8; ++u)
#pragma unroll
                for (int v = 0; v < 8; ++v)
                    acc[u][v] = fmaf(a[u], b[v], acc[u][v]);
        }
#pragma unroll
        for (int p = 0; p < 8; ++p) {
            int e = tid + 256 * p, r = e >> 4, c = e & 15;
            As[buf ^ 1][c][r] = pa[p];
            Bs[buf ^ 1][c][r] = pb[p];
        }
        __syncthreads();
        buf ^= 1;
    }
    // last tile
#pragma unroll
    for (int k = 0; k < BK; ++k) {
        float a[8], b[8];
        *(float4*)&a[0] = *(const float4*)&As[buf][k][ty * 8];
        *(float4*)&a[4] = *(const float4*)&As[buf][k][ty * 8 + 4];
        *(float4*)&b[0] = *(const float4*)&Bs[buf][k][tx * 8];
        *(float4*)&b[4] = *(const float4*)&Bs[buf][k][tx * 8 + 4];
#pragma unroll
        for (int u = 0; u < 8; ++u)
#pragma unroll
            for (int v = 0; v < 8; ++v)
                acc[u][v] = fmaf(a[u], b[v], acc[u][v]);
    }

    dist_store(acc, x2v, D, i0, j0, tx, ty, bx != by);
}

// ------------------------- tiled fp32 GEMM (MLP, double-buffered) -----------
// C[i,j] = relu(dot(A_i, W[:,j]) + bias[j]),  W row-major [K,N].
__global__ __launch_bounds__(256, 2) void gemm_kernel(
    const float* __restrict__ A, int lda,
    const float* __restrict__ B, int ldb,
    const float* __restrict__ bias,
    float* __restrict__ Cout, int ldc,
    int N, int K) {
    __shared__ float As[2][BK][BM + 4];
    __shared__ float Bs[2][BK][BN + 4];

    const int tid = threadIdx.x;
    const int tx = tid & 15, ty = tid >> 4;
    const int i0 = blockIdx.y * BM;
    const int j0 = blockIdx.x * BN;

    float acc[8][8];
#pragma unroll
    for (int u = 0; u < 8; ++u)
#pragma unroll
        for (int v = 0; v < 8; ++v) acc[u][v] = 0.f;

#pragma unroll
    for (int p = 0; p < 8; ++p) {
        int e = tid + 256 * p;
        {
            int r = e >> 4, c = e & 15;
            As[0][c][r] = (c < K) ? A[(size_t)(i0 + r) * lda + c] : 0.f;
        }
        {
            int r = e >> 7, c = e & 127;
            Bs[0][r][c] = (r < K && j0 + c < N)
                              ? B[(size_t)r * ldb + j0 + c] : 0.f;
        }
    }
    __syncthreads();

    const int nt = (K + BK - 1) / BK;
    int buf = 0;
    for (int t = 1; t < nt; ++t) {
        const int kk = t * BK;
        float pa[8], pb[8];
#pragma unroll
        for (int p = 0; p < 8; ++p) {
            int e = tid + 256 * p;
            {
                int r = e >> 4, c = e & 15;
                pa[p] = (kk + c < K) ? A[(size_t)(i0 + r) * lda + kk + c] : 0.f;
            }
            {
                int r = e >> 7, c = e & 127;
                pb[p] = (kk + r < K && j0 + c < N)
                            ? B[(size_t)(kk + r) * ldb + j0 + c] : 0.f;
            }
        }
#pragma unroll
        for (int k = 0; k < BK; ++k) {
            float a[8], b[8];
            *(float4*)&a[0] = *(const float4*)&As[buf][k][ty * 8];
            *(float4*)&a[4] = *(const float4*)&As[buf][k][ty * 8 + 4];
            *(float4*)&b[0] = *(const float4*)&Bs[buf][k][tx * 8];
            *(float4*)&b[4] = *(const float4*)&Bs[buf][k][tx * 8 + 4];
#pragma unroll
            for (int u = 0; u < 8; ++u)
#pragma unroll
                for (int v = 0; v < 8; ++v)
                    acc[u][v] = fmaf(a[u], b[v], acc[u][v]);
        }
#pragma unroll
        for (int p = 0; p < 8; ++p) {
            int e = tid + 256 * p;
            { int r = e >> 4, c = e & 15;  As[buf ^ 1][c][r] = pa[p]; }
            { int r = e >> 7, c = e & 127; Bs[buf ^ 1][r][c] = pb[p]; }
        }
        __syncthreads();
        buf ^= 1;
    }
#pragma unroll
    for (int k = 0; k < BK; ++k) {
        float a[8], b[8];
        *(float4*)&a[0] = *(const float4*)&As[buf][k][ty * 8];
        *(float4*)&a[4] = *(const float4*)&As[buf][k][ty * 8 + 4];
        *(float4*)&b[0] = *(const float4*)&Bs[buf][k][tx * 8];
        *(float4*)&b[4] = *(const float4*)&Bs[buf][k][tx * 8 + 4];
#pragma unroll
        for (int u = 0; u < 8; ++u)
#pragma unroll
            for (int v = 0; v < 8; ++v)
                acc[u][v] = fmaf(a[u], b[v], acc[u][v]);
    }

#pragma unroll
    for (int u = 0; u < 8; ++u) {
        int i = i0 + ty * 8 + u;
#pragma unroll
        for (int v = 0; v < 8; ++v) {
            int j = j0 + tx * 8 + v;
            if (j < N)
                Cout[(size_t)i * ldc + j] =
                    fmaxf(__fadd_rn(acc[u][v], bias[j]), 0.f);
        }
    }
}

// ------------------------- top-20 selection (warp per row) ------------------
__global__ void topk_kernel(const float* __restrict__ D, int* __restrict__ out) {
    __shared__ float sd[8][KNN];
    __shared__ int   si[8][KNN];

    const int lane = threadIdx.x & 31;
    const int wloc = threadIdx.x >> 5;
    const int row  = (blockIdx.x * blockDim.x + threadIdx.x) >> 5;

    if (lane < KNN) { sd[wloc][lane] = FLT_MAX; si[wloc][lane] = 0x7fffffff; }
    __syncwarp();

    const float* r = D + (size_t)row * NPTS;
    float thresh = FLT_MAX;

    for (int base = 0; base < NPTS; base += 32) {
        float d = r[base + lane];
        unsigned m = __ballot_sync(0xffffffffu, d < thresh);
        while (m) {
            int src = __ffs(m) - 1;
            m &= m - 1;
            float dc = __shfl_sync(0xffffffffu, d, src);
            int   jc = base + src;
            if (lane == 0) {
                if (dc < sd[wloc][KNN - 1]) {
                    int p = KNN - 1;
                    while (p > 0 && sd[wloc][p - 1] > dc) {
                        sd[wloc][p] = sd[wloc][p - 1];
                        si[wloc][p] = si[wloc][p - 1];
                        --p;
                    }
                    sd[wloc][p] = dc;
                    si[wloc][p] = jc;
                }
            }
            __syncwarp();
            thresh = sd[wloc][KNN - 1];
        }
    }
    if (lane < KNN) out[row * KNN + lane] = si[wloc][lane];
}

// ------------------------- erosion EdgeConv ---------------------------------
__global__ void erode_kernel(const float* __restrict__ Xin, int ldin,
                             const int* __restrict__ idx,
                             const float* __restrict__ w,
                             float* __restrict__ out, int ldout,
                             int F, int C) {
    __shared__ float nb[KNN * 120];    // max C = 120
    const int i = blockIdx.x;
    const int* ip = idx + i * KNN;

    for (int e = threadIdx.x; e < KNN * C; e += blockDim.x) {
        int k = e / C, c = e - k * C;
        nb[e] = Xin[(size_t)ip[k] * ldin + c];
    }
    __syncthreads();

    for (int e = threadIdx.x; e < F * C; e += blockDim.x) {
        int f = e / C, c = e - f * C;
        float mn = FLT_MAX;
        const float* wf = w + (size_t)f * KNN * C + c;
#pragma unroll 4
        for (int k = 0; k < KNN; ++k)
            mn = fminf(mn, __fsub_rn(nb[k * C + c], wf[k * C]));
        out[(size_t)i * ldout + e] = mn;
    }
}

// ------------------------- final linear + log_softmax -----------------------
__global__ void head_kernel(const float* __restrict__ H,
                            const float* __restrict__ wo,
                            const float* __restrict__ bo,
                            float* __restrict__ out) {
    __shared__ float h[128];
    __shared__ float lg[40];
    __shared__ float s_lse;
    const int i = blockIdx.x;
    const int t = threadIdx.x;              // 128 threads

    h[t] = H[(size_t)i * 128 + t];
    __syncthreads();

    if (t < 40) {
        float s = 0.f;
#pragma unroll 8
        for (int k = 0; k < 128; ++k) s = fmaf(h[k], wo[k * 40 + t], s);
        lg[t] = __fadd_rn(s, bo[t]);
    }
    __syncthreads();

    if (t == 0) {
        float m = -FLT_MAX;
        for (int n = 0; n < 40; ++n) m = fmaxf(m, lg[n]);
        float s = 0.f;
        for (int n = 0; n < 40; ++n) s = __fadd_rn(s, expf(__fsub_rn(lg[n], m)));
        s_lse = __fadd_rn(m, logf(s));
    }
    __syncthreads();

    if (t < 40) out[(size_t)i * 40 + t] = __fsub_rn(lg[t], s_lse);
}

// ------------------------- launch sequence ----------------------------------
extern "C" void kernel_launch(void* const* d_in, const int* in_sizes, int n_in,
                              void* d_out, int out_size) {
    const float* x      = (const float*)d_in[0];
    const float* w1     = (const float*)d_in[1];
    const float* w2     = (const float*)d_in[2];
    const float* w3     = (const float*)d_in[3];
    const float* lin1_w = (const float*)d_in[4];
    const float* lin1_b = (const float*)d_in[5];
    const float* wa     = (const float*)d_in[6];
    const float* ba     = (const float*)d_in[7];
    const float* wb     = (const float*)d_in[8];
    const float* bb     = (const float*)d_in[9];
    const float* wo     = (const float*)d_in[10];
    const float* bo     = (const float*)d_in[11];
    float* out = (float*)d_out;

    float *D, *x2, *cat, *h1, *h2, *h3;
    int* idxp;
    cudaGetSymbolAddress((void**)&D,   g_D);
    cudaGetSymbolAddress((void**)&x2,  g_x2);
    cudaGetSymbolAddress((void**)&idxp,g_idx);
    cudaGetSymbolAddress((void**)&cat, g_cat);
    cudaGetSymbolAddress((void**)&h1,  g_h1);
    cudaGetSymbolAddress((void**)&h2,  g_h2);
    cudaGetSymbolAddress((void**)&h3,  g_h3);

    const int NB = NPTS / BM;                 // 64 tiles per dim
    const int NTRI = NB * (NB + 1) / 2;       // 2080 lower-triangle blocks

    const int smem_knn3 = (4 * NPTS + 32 * KNN) * (int)sizeof(float)
                        + 32 * KNN * (int)sizeof(int);   // ~133 KB
    cudaFuncSetAttribute(knn3_kernel,
                         cudaFuncAttributeMaxDynamicSharedMemorySize, smem_knn3);

    // ---- layer 1: kNN on x (C=3) fused (no D matrix), erode -> cat[:, 0:60]
    sqnorm_seq_kernel<<<32, 256>>>(x, 3, 3, x2);
    knn3_kernel<<<NPTS / 32, 1024, smem_knn3>>>(x, x2, idxp);
    erode_kernel<<<NPTS, 128>>>(x, 3, idxp, w1, cat, 420, 20, 3);

    // ---- layer 2: kNN on x1 (C=60), erode -> cat[:, 60:180]
    sqnorm_warp_kernel<<<NPTS / 8, 256>>>(cat, 420, 60, x2);
    dist_sym_kernel<<<NTRI, 256>>>(cat, 420, x2, D, 60);
    topk_kernel<<<NPTS / 8, 256>>>(D, idxp);
    erode_kernel<<<NPTS, 128>>>(cat, 420, idxp, w2, cat + 60, 420, 2, 60);

    // ---- layer 3: kNN on x2 (C=120), erode -> cat[:, 180:420]
    sqnorm_warp_kernel<<<NPTS / 8, 256>>>(cat + 60, 420, 120, x2);
    dist_sym_kernel<<<NTRI, 256>>>(cat + 60, 420, x2, D, 120);
    topk_kernel<<<NPTS / 8, 256>>>(D, idxp);
    erode_kernel<<<NPTS, 128>>>(cat + 60, 420, idxp, w3, cat + 180, 420, 2, 120);

    // ---- MLP head
    gemm_kernel<<<dim3(1024 / BN, NPTS / BM), 256>>>(
        cat, 420, lin1_w, 1024, lin1_b, h1, 1024, 1024, 420);
    gemm_kernel<<<dim3(2, NPTS / BM), 256>>>(
        h1, 1024, wa, 256, ba, h2, 256, 256, 1024);
    gemm_kernel<<<dim3(1, NPTS / BM), 256>>>(
        h2, 256, wb, 128, bb, h3, 128, 128, 256);

    head_kernel<<<NPTS, 128>>>(h3, wo, bo, out);
}

// round 13
// speedup vs baseline: 1.1277x; 1.0237x over previous
#include <cuda_runtime.h>
#include <math.h>
#include <float.h>

#define NPTS 8192
#define KNN  20

// ------------------------- scratch (__device__ globals, no allocation) ------
__device__ float g_D[(size_t)NPTS * NPTS];   // 256 MB dist matrix
__device__ float g_x2[NPTS];
__device__ int   g_idx[NPTS * KNN];
__device__ float g_cat[NPTS * 420];          // x1|x2|x3 concatenated (60|120|240)
__device__ float g_h1[NPTS * 1024];
__device__ float g_h2[NPTS * 256];
__device__ float g_h3[NPTS * 128];

// ------------------------- packed f32x2 FMA ---------------------------------
// fma.rn.f32x2 (Blackwell, PTX ISA 8.6+): TWO independent IEEE-RN fp32 FMAs
// per instruction (SASS FFMA2) -- bitwise identical to two scalar fmaf, at
// half the FMA-pipe instruction count. ptxas never auto-generates it.
__device__ __forceinline__ unsigned long long ffma2(
    unsigned long long a, unsigned long long b, unsigned long long c) {
    unsigned long long d;
    asm("fma.rn.f32x2 %0, %1, %2, %3;" : "=l"(d) : "l"(a), "l"(b), "l"(c));
    return d;
}
__device__ __forceinline__ unsigned long long pack2(float x) {
    unsigned long long d;
    asm("mov.b64 %0, {%1, %2};" : "=l"(d) : "f"(x), "f"(x));
    return d;
}
__device__ __forceinline__ void unpack2(unsigned long long p, float& lo, float& hi) {
    asm("mov.b64 {%0, %1}, %2;" : "=f"(lo), "=f"(hi) : "l"(p));
}

// ------------------------- squared norms ------------------------------------
// Frozen arithmetic recipe (matches reference bit-for-bit on ranking path).
__global__ void sqnorm_seq_kernel(const float* __restrict__ X, int ld, int C,
                                  float* __restrict__ x2) {
    int i = blockIdx.x * blockDim.x + threadIdx.x;
    if (i >= NPTS) return;
    const float* r = X + (size_t)i * ld;
    float s = 0.f;
    for (int c = 0; c < C; ++c)
        s = __fadd_rn(s, __fmul_rn(r[c], r[c]));
    x2[i] = s;
}

__global__ void sqnorm_warp_kernel(const float* __restrict__ X, int ld, int C,
                                   float* __restrict__ x2) {
    const int lane = threadIdx.x & 31;
    const int row  = (blockIdx.x * blockDim.x + threadIdx.x) >> 5;
    if (row >= NPTS) return;

    const float* r = X + (size_t)row * ld;
    float s = 0.f;
    for (int c = lane; c < C; c += 32)
        s = __fadd_rn(s, __fmul_rn(r[c], r[c]));
#pragma unroll
    for (int off = 16; off > 0; off >>= 1)
        s = __fadd_rn(s, __shfl_down_sync(0xffffffffu, s, off));
    if (lane == 0) x2[row] = s;
}

#define BM 128
#define BN 128
#define BK 16

// triangle decode: linear block id -> (bx, by), by <= bx
__device__ __forceinline__ void tri_decode(int t, int& bx, int& by) {
    bx = (int)((sqrtf(8.f * (float)t + 1.f) - 1.f) * 0.5f);
    while ((bx + 1) * (bx + 2) / 2 <= t) ++bx;
    while (bx * (bx + 1) / 2 > t) --bx;
    by = t - bx * (bx + 1) / 2;
}

// epilogue + symmetric dual store (scalar chain, unchanged)
__device__ __forceinline__ void dist_store(float acc[8][8],
                                           const float* __restrict__ x2v,
                                           float* __restrict__ D,
                                           int i0, int j0, int tx, int ty,
                                           bool offdiag) {
    float res[8][8];
#pragma unroll
    for (int u = 0; u < 8; ++u) {
        int i = i0 + ty * 8 + u;
#pragma unroll
        for (int v = 0; v < 8; ++v) {
            int j = j0 + tx * 8 + v;
            float s = __fadd_rn(x2v[i], x2v[j]);
            res[u][v] = __fsub_rn(s, __fmul_rn(2.f, acc[u][v]));
        }
    }
#pragma unroll
    for (int u = 0; u < 8; ++u) {
        int i = i0 + ty * 8 + u;
        *(float4*)&D[(size_t)i * NPTS + j0 + tx * 8]     = *(float4*)&res[u][0];
        *(float4*)&D[(size_t)i * NPTS + j0 + tx * 8 + 4] = *(float4*)&res[u][4];
    }
    if (offdiag) {
#pragma unroll
        for (int v = 0; v < 8; ++v) {
            int j = j0 + tx * 8 + v;
            float4 p0 = make_float4(res[0][v], res[1][v], res[2][v], res[3][v]);
            float4 p1 = make_float4(res[4][v], res[5][v], res[6][v], res[7][v]);
            *(float4*)&D[(size_t)j * NPTS + i0 + ty * 8]     = p0;
            *(float4*)&D[(size_t)j * NPTS + i0 + ty * 8 + 4] = p1;
        }
    }
}

// ------------------------- fused kNN for C=3 (no D matrix) ------------------
__global__ __launch_bounds__(1024, 1) void knn3_kernel(
    const float* __restrict__ X,
    const float* __restrict__ x2v,
    int* __restrict__ out) {
    extern __shared__ float sm[];
    float* A0 = sm;
    float* A1 = sm + NPTS;
    float* A2 = sm + 2 * NPTS;
    float* X2 = sm + 3 * NPTS;
    float* sd = X2 + NPTS;                     // [32][KNN]
    int*   si = (int*)(sd + 32 * KNN);         // [32][KNN]

    const int tid = threadIdx.x;
    for (int j = tid; j < NPTS; j += 1024) {
        const float* p = X + (size_t)j * 3;
        A0[j] = p[0]; A1[j] = p[1]; A2[j] = p[2];
        X2[j] = x2v[j];
    }
    __syncthreads();

    const int lane = tid & 31;
    const int w    = tid >> 5;                 // 32 warps
    const int row  = blockIdx.x * 32 + w;

    const float a0 = A0[row], a1 = A1[row], a2 = A2[row];
    const float xi = X2[row];

    float* wd = sd + w * KNN;
    int*   wi = si + w * KNN;
    if (lane < KNN) { wd[lane] = FLT_MAX; wi[lane] = 0x7fffffff; }
    __syncwarp();

    float thresh = FLT_MAX;
    for (int base = 0; base < NPTS; base += 32) {
        const int j = base + lane;
        float acc = fmaf(a0, A0[j], 0.f);
        acc = fmaf(a1, A1[j], acc);
        acc = fmaf(a2, A2[j], acc);
        float d = __fsub_rn(__fadd_rn(xi, X2[j]), __fmul_rn(2.f, acc));

        unsigned m = __ballot_sync(0xffffffffu, d < thresh);
        while (m) {
            int src = __ffs(m) - 1;
            m &= m - 1;
            float dc = __shfl_sync(0xffffffffu, d, src);
            int   jc = base + src;
            if (lane == 0) {
                if (dc < wd[KNN - 1]) {
                    int p = KNN - 1;
                    while (p > 0 && wd[p - 1] > dc) {
                        wd[p] = wd[p - 1];
                        wi[p] = wi[p - 1];
                        --p;
                    }
                    wd[p] = dc;
                    wi[p] = jc;
                }
            }
            __syncwarp();
            thresh = wd[KNN - 1];
        }
    }
    if (lane < KNN) out[row * KNN + lane] = wi[lane];
}

// ------------------------- symmetric pairwise distance (FFMA2 mainloop) -----
// Accumulators packed along v: acc2[u][p] = (v=2p, v=2p+1). b pairs are free
// (reinterpret the 16B smem loads); a is duplicated via one mov.b64 per u per
// k (ALU pipe). Per-element accumulation chain identical -> bitwise output.
__global__ __launch_bounds__(256, 2) void dist_sym_kernel(
    const float* __restrict__ X, int ld,
    const float* __restrict__ x2v,
    float* __restrict__ D, int K) {
    __shared__ float As[2][BK][BM + 4];
    __shared__ float Bs[2][BK][BN + 4];

    int bx, by;
    tri_decode(blockIdx.x, bx, by);
    const int i0 = bx * BM, j0 = by * BN;
    const int tid = threadIdx.x;
    const int tx = tid & 15, ty = tid >> 4;

    unsigned long long acc2[8][4];
#pragma unroll
    for (int u = 0; u < 8; ++u)
#pragma unroll
        for (int p = 0; p < 4; ++p) acc2[u][p] = 0ull;   // {+0f,+0f}

    // prologue: tile 0
#pragma unroll
    for (int p = 0; p < 8; ++p) {
        int e = tid + 256 * p, r = e >> 4, c = e & 15;
        As[0][c][r] = (c < K) ? X[(size_t)(i0 + r) * ld + c] : 0.f;
        Bs[0][c][r] = (c < K) ? X[(size_t)(j0 + r) * ld + c] : 0.f;
    }
    __syncthreads();

    const int nt = (K + BK - 1) / BK;
    int buf = 0;
    for (int t = 1; t < nt; ++t) {
        const int kk = t * BK;
        float pa[8], pb[8];
#pragma unroll
        for (int p = 0; p < 8; ++p) {
            int e = tid + 256 * p, r = e >> 4, c = e & 15;
            pa[p] = (kk + c < K) ? X[(size_t)(i0 + r) * ld + kk + c] : 0.f;
            pb[p] = (kk + c < K) ? X[(size_t)(j0 + r) * ld + kk + c] : 0.f;
        }
#pragma unroll
        for (int k = 0; k < BK; ++k) {
            float a[8];
            *(float4*)&a[0] = *(const float4*)&As[buf][k][ty * 8];
            *(float4*)&a[4] = *(const float4*)&As[buf][k][ty * 8 + 4];
            ulonglong2 t0 = *(const ulonglong2*)&Bs[buf][k][tx * 8];
            ulonglong2 t1 = *(const ulonglong2*)&Bs[buf][k][tx * 8 + 4];
            unsigned long long b2[4] = {t0.x, t0.y, t1.x, t1.y};
#pragma unroll
            for (int u = 0; u < 8; ++u) {
                unsigned long long a2 = pack2(a[u]);
#pragma unroll
                for (int p = 0; p < 4; ++p)
                    acc2[u][p] = ffma2(a2, b2[p], acc2[u][p]);
            }
        }
#pragma unroll
        for (int p = 0; p < 8; ++p) {
            int e = tid + 256 * p, r = e >> 4, c = e & 15;
            As[buf ^ 1][c][r] = pa[p];
            Bs[buf ^ 1][c][r] = pb[p];
        }
        __syncthreads();
        buf ^= 1;
    }
    // last tile
#pragma unroll
    for (int k = 0; k < BK; ++k) {
        float a[8];
        *(float4*)&a[0] = *(const float4*)&As[buf][k][ty * 8];
        *(float4*)&a[4] = *(const float4*)&As[buf][k][ty * 8 + 4];
        ulonglong2 t0 = *(const ulonglong2*)&Bs[buf][k][tx * 8];
        ulonglong2 t1 = *(const ulonglong2*)&Bs[buf][k][tx * 8 + 4];
        unsigned long long b2[4] = {t0.x, t0.y, t1.x, t1.y};
#pragma unroll
        for (int u = 0; u < 8; ++u) {
            unsigned long long a2 = pack2(a[u]);
#pragma unroll
            for (int p = 0; p < 4; ++p)
                acc2[u][p] = ffma2(a2, b2[p], acc2[u][p]);
        }
    }

    float acc[8][8];
#pragma unroll
    for (int u = 0; u < 8; ++u)
#pragma unroll
        for (int p = 0; p < 4; ++p)
            unpack2(acc2[u][p], acc[u][2 * p], acc[u][2 * p + 1]);

    dist_store(acc, x2v, D, i0, j0, tx, ty, bx != by);
}

// ------------------------- tiled fp32 GEMM (MLP, FFMA2 mainloop) ------------
__global__ __launch_bounds__(256, 2) void gemm_kernel(
    const float* __restrict__ A, int lda,
    const float* __restrict__ B, int ldb,
    const float* __restrict__ bias,
    float* __restrict__ Cout, int ldc,
    int N, int K) {
    __shared__ float As[2][BK][BM + 4];
    __shared__ float Bs[2][BK][BN + 4];

    const int tid = threadIdx.x;
    const int tx = tid & 15, ty = tid >> 4;
    const int i0 = blockIdx.y * BM;
    const int j0 = blockIdx.x * BN;

    unsigned long long acc2[8][4];
#pragma unroll
    for (int u = 0; u < 8; ++u)
#pragma unroll
        for (int p = 0; p < 4; ++p) acc2[u][p] = 0ull;

#pragma unroll
    for (int p = 0; p < 8; ++p) {
        int e = tid + 256 * p;
        {
            int r = e >> 4, c = e & 15;
            As[0][c][r] = (c < K) ? A[(size_t)(i0 + r) * lda + c] : 0.f;
        }
        {
            int r = e >> 7, c = e & 127;
            Bs[0][r][c] = (r < K && j0 + c < N)
                              ? B[(size_t)r * ldb + j0 + c] : 0.f;
        }
    }
    __syncthreads();

    const int nt = (K + BK - 1) / BK;
    int buf = 0;
    for (int t = 1; t < nt; ++t) {
        const int kk = t * BK;
        float pa[8], pb[8];
#pragma unroll
        for (int p = 0; p < 8; ++p) {
            int e = tid + 256 * p;
            {
                int r = e >> 4, c = e & 15;
                pa[p] = (kk + c < K) ? A[(size_t)(i0 + r) * lda + kk + c] : 0.f;
            }
            {
                int r = e >> 7, c = e & 127;
                pb[p] = (kk + r < K && j0 + c < N)
                            ? B[(size_t)(kk + r) * ldb + j0 + c] : 0.f;
            }
        }
#pragma unroll
        for (int k = 0; k < BK; ++k) {
            float a[8];
            *(float4*)&a[0] = *(const float4*)&As[buf][k][ty * 8];
            *(float4*)&a[4] = *(const float4*)&As[buf][k][ty * 8 + 4];
            ulonglong2 t0 = *(const ulonglong2*)&Bs[buf][k][tx * 8];
            ulonglong2 t1 = *(const ulonglong2*)&Bs[buf][k][tx * 8 + 4];
            unsigned long long b2[4] = {t0.x, t0.y, t1.x, t1.y};
#pragma unroll
            for (int u = 0; u < 8; ++u) {
                unsigned long long a2 = pack2(a[u]);
#pragma unroll
                for (int p = 0; p < 4; ++p)
                    acc2[u][p] = ffma2(a2, b2[p], acc2[u][p]);
            }
        }
#pragma unroll
        for (int p = 0; p < 8; ++p) {
            int e = tid + 256 * p;
            { int r = e >> 4, c = e & 15;  As[buf ^ 1][c][r] = pa[p]; }
            { int r = e >> 7, c = e & 127; Bs[buf ^ 1][r][c] = pb[p]; }
        }
        __syncthreads();
        buf ^= 1;
    }
#pragma unroll
    for (int k = 0; k < BK; ++k) {
        float a[8];
        *(float4*)&a[0] = *(const float4*)&As[buf][k][ty * 8];
        *(float4*)&a[4] = *(const float4*)&As[buf][k][ty * 8 + 4];
        ulonglong2 t0 = *(const ulonglong2*)&Bs[buf][k][tx * 8];
        ulonglong2 t1 = *(const ulonglong2*)&Bs[buf][k][tx * 8 + 4];
        unsigned long long b2[4] = {t0.x, t0.y, t1.x, t1.y};
#pragma unroll
        for (int u = 0; u < 8; ++u) {
            unsigned long long a2 = pack2(a[u]);
#pragma unroll
            for (int p = 0; p < 4; ++p)
                acc2[u][p] = ffma2(a2, b2[p], acc2[u][p]);
        }
    }

    float acc[8][8];
#pragma unroll
    for (int u = 0; u < 8; ++u)
#pragma unroll
        for (int p = 0; p < 4; ++p)
            unpack2(acc2[u][p], acc[u][2 * p], acc[u][2 * p + 1]);

#pragma unroll
    for (int u = 0; u < 8; ++u) {
        int i = i0 + ty * 8 + u;
#pragma unroll
        for (int v = 0; v < 8; ++v) {
            int j = j0 + tx * 8 + v;
            if (j < N)
                Cout[(size_t)i * ldc + j] =
                    fmaxf(__fadd_rn(acc[u][v], bias[j]), 0.f);
        }
    }
}

// ------------------------- top-20 selection (warp per row) ------------------
__global__ void topk_kernel(const float* __restrict__ D, int* __restrict__ out) {
    __shared__ float sd[8][KNN];
    __shared__ int   si[8][KNN];

    const int lane = threadIdx.x & 31;
    const int wloc = threadIdx.x >> 5;
    const int row  = (blockIdx.x * blockDim.x + threadIdx.x) >> 5;

    if (lane < KNN) { sd[wloc][lane] = FLT_MAX; si[wloc][lane] = 0x7fffffff; }
    __syncwarp();

    const float* r = D + (size_t)row * NPTS;
    float thresh = FLT_MAX;

    for (int base = 0; base < NPTS; base += 32) {
        float d = r[base + lane];
        unsigned m = __ballot_sync(0xffffffffu, d < thresh);
        while (m) {
            int src = __ffs(m) - 1;
            m &= m - 1;
            float dc = __shfl_sync(0xffffffffu, d, src);
            int   jc = base + src;
            if (lane == 0) {
                if (dc < sd[wloc][KNN - 1]) {
                    int p = KNN - 1;
                    while (p > 0 && sd[wloc][p - 1] > dc) {
                        sd[wloc][p] = sd[wloc][p - 1];
                        si[wloc][p] = si[wloc][p - 1];
                        --p;
                    }
                    sd[wloc][p] = dc;
                    si[wloc][p] = jc;
                }
            }
            __syncwarp();
            thresh = sd[wloc][KNN - 1];
        }
    }
    if (lane < KNN) out[row * KNN + lane] = si[wloc][lane];
}

// ------------------------- erosion EdgeConv ---------------------------------
__global__ void erode_kernel(const float* __restrict__ Xin, int ldin,
                             const int* __restrict__ idx,
                             const float* __restrict__ w,
                             float* __restrict__ out, int ldout,
                             int F, int C) {
    __shared__ float nb[KNN * 120];    // max C = 120
    const int i = blockIdx.x;
    const int* ip = idx + i * KNN;

    for (int e = threadIdx.x; e < KNN * C; e += blockDim.x) {
        int k = e / C, c = e - k * C;
        nb[e] = Xin[(size_t)ip[k] * ldin + c];
    }
    __syncthreads();

    for (int e = threadIdx.x; e < F * C; e += blockDim.x) {
        int f = e / C, c = e - f * C;
        float mn = FLT_MAX;
        const float* wf = w + (size_t)f * KNN * C + c;
#pragma unroll 4
        for (int k = 0; k < KNN; ++k)
            mn = fminf(mn, __fsub_rn(nb[k * C + c], wf[k * C]));
        out[(size_t)i * ldout + e] = mn;
    }
}

// ------------------------- final linear + log_softmax -----------------------
__global__ void head_kernel(const float* __restrict__ H,
                            const float* __restrict__ wo,
                            const float* __restrict__ bo,
                            float* __restrict__ out) {
    __shared__ float h[128];
    __shared__ float lg[40];
    __shared__ float s_lse;
    const int i = blockIdx.x;
    const int t = threadIdx.x;              // 128 threads

    h[t] = H[(size_t)i * 128 + t];
    __syncthreads();

    if (t < 40) {
        float s = 0.f;
#pragma unroll 8
        for (int k = 0; k < 128; ++k) s = fmaf(h[k], wo[k * 40 + t], s);
        lg[t] = __fadd_rn(s, bo[t]);
    }
    __syncthreads();

    if (t == 0) {
        float m = -FLT_MAX;
        for (int n = 0; n < 40; ++n) m = fmaxf(m, lg[n]);
        float s = 0.f;
        for (int n = 0; n < 40; ++n) s = __fadd_rn(s, expf(__fsub_rn(lg[n], m)));
        s_lse = __fadd_rn(m, logf(s));
    }
    __syncthreads();

    if (t < 40) out[(size_t)i * 40 + t] = __fsub_rn(lg[t], s_lse);
}

// ------------------------- launch sequence ----------------------------------
extern "C" void kernel_launch(void* const* d_in, const int* in_sizes, int n_in,
                              void* d_out, int out_size) {
    const float* x      = (const float*)d_in[0];
    const float* w1     = (const float*)d_in[1];
    const float* w2     = (const float*)d_in[2];
    const float* w3     = (const float*)d_in[3];
    const float* lin1_w = (const float*)d_in[4];
    const float* lin1_b = (const float*)d_in[5];
    const float* wa     = (const float*)d_in[6];
    const float* ba     = (const float*)d_in[7];
    const float* wb     = (const float*)d_in[8];
    const float* bb     = (const float*)d_in[9];
    const float* wo     = (const float*)d_in[10];
    const float* bo     = (const float*)d_in[11];
    float* out = (float*)d_out;

    float *D, *x2, *cat, *h1, *h2, *h3;
    int* idxp;
    cudaGetSymbolAddress((void**)&D,   g_D);
    cudaGetSymbolAddress((void**)&x2,  g_x2);
    cudaGetSymbolAddress((void**)&idxp,g_idx);
    cudaGetSymbolAddress((void**)&cat, g_cat);
    cudaGetSymbolAddress((void**)&h1,  g_h1);
    cudaGetSymbolAddress((void**)&h2,  g_h2);
    cudaGetSymbolAddress((void**)&h3,  g_h3);

    const int NB = NPTS / BM;                 // 64 tiles per dim
    const int NTRI = NB * (NB + 1) / 2;       // 2080 lower-triangle blocks

    const int smem_knn3 = (4 * NPTS + 32 * KNN) * (int)sizeof(float)
                        + 32 * KNN * (int)sizeof(int);   // ~133 KB
    cudaFuncSetAttribute(knn3_kernel,
                         cudaFuncAttributeMaxDynamicSharedMemorySize, smem_knn3);

    // ---- layer 1: kNN on x (C=3) fused (no D matrix), erode -> cat[:, 0:60]
    sqnorm_seq_kernel<<<32, 256>>>(x, 3, 3, x2);
    knn3_kernel<<<NPTS / 32, 1024, smem_knn3>>>(x, x2, idxp);
    erode_kernel<<<NPTS, 128>>>(x, 3, idxp, w1, cat, 420, 20, 3);

    // ---- layer 2: kNN on x1 (C=60), erode -> cat[:, 60:180]
    sqnorm_warp_kernel<<<NPTS / 8, 256>>>(cat, 420, 60, x2);
    dist_sym_kernel<<<NTRI, 256>>>(cat, 420, x2, D, 60);
    topk_kernel<<<NPTS / 8, 256>>>(D, idxp);
    erode_kernel<<<NPTS, 128>>>(cat, 420, idxp, w2, cat + 60, 420, 2, 60);

    // ---- layer 3: kNN on x2 (C=120), erode -> cat[:, 180:420]
    sqnorm_warp_kernel<<<NPTS / 8, 256>>>(cat + 60, 420, 120, x2);
    dist_sym_kernel<<<NTRI, 256>>>(cat + 60, 420, x2, D, 120);
    topk_kernel<<<NPTS / 8, 256>>>(D, idxp);
    erode_kernel<<<NPTS, 128>>>(cat + 60, 420, idxp, w3, cat + 180, 420, 2, 120);

    // ---- MLP head
    gemm_kernel<<<dim3(1024 / BN, NPTS / BM), 256>>>(
        cat, 420, lin1_w, 1024, lin1_b, h1, 1024, 1024, 420);
    gemm_kernel<<<dim3(2, NPTS / BM), 256>>>(
        h1, 1024, wa, 256, ba, h2, 256, 256, 1024);
    gemm_kernel<<<dim3(1, NPTS / BM), 256>>>(
        h2, 256, wb, 128, bb, h3, 128, 128, 256);

    head_kernel<<<NPTS, 128>>>(h3, wo, bo, out);
}

// round 14
// speedup vs baseline: 1.2035x; 1.0672x over previous
#include <cuda_runtime.h>
#include <math.h>
#include <float.h>

#define NPTS 8192
#define KNN  20

// ------------------------- scratch (__device__ globals, no allocation) ------
__device__ float g_D[(size_t)NPTS * NPTS];   // 256 MB dist matrix
__device__ float g_x2[NPTS];
__device__ int   g_idx[NPTS * KNN];
__device__ float g_cat[NPTS * 420];          // x1|x2|x3 concatenated (60|120|240)
__device__ float g_h1[NPTS * 1024];
__device__ float g_h2[NPTS * 256];
__device__ float g_h3[NPTS * 128];

// ------------------------- packed f32x2 FMA ---------------------------------
// fma.rn.f32x2: two independent IEEE-RN fp32 FMAs per instruction. Bitwise
// identical halves; keeps issue slots low (throughput-neutral on FMA pipe).
__device__ __forceinline__ unsigned long long ffma2(
    unsigned long long a, unsigned long long b, unsigned long long c) {
    unsigned long long d;
    asm("fma.rn.f32x2 %0, %1, %2, %3;" : "=l"(d) : "l"(a), "l"(b), "l"(c));
    return d;
}
__device__ __forceinline__ unsigned long long pack2(float x) {
    unsigned long long d;
    asm("mov.b64 %0, {%1, %2};" : "=l"(d) : "f"(x), "f"(x));
    return d;
}
__device__ __forceinline__ void unpack2(unsigned long long p, float& lo, float& hi) {
    asm("mov.b64 {%0, %1}, %2;" : "=f"(lo), "=f"(hi) : "l"(p));
}

// ------------------------- squared norms (layer 1 only) ---------------------
// Frozen recipe, C small: one thread per row, sequential separately-rounded.
__global__ void sqnorm_seq_kernel(const float* __restrict__ X, int ld, int C,
                                  float* __restrict__ x2) {
    int i = blockIdx.x * blockDim.x + threadIdx.x;
    if (i >= NPTS) return;
    const float* r = X + (size_t)i * ld;
    float s = 0.f;
    for (int c = 0; c < C; ++c)
        s = __fadd_rn(s, __fmul_rn(r[c], r[c]));
    x2[i] = s;
}

#define BM 128
#define BN 128
#define BK 16

// triangle decode: linear block id -> (bx, by), by <= bx
__device__ __forceinline__ void tri_decode(int t, int& bx, int& by) {
    bx = (int)((sqrtf(8.f * (float)t + 1.f) - 1.f) * 0.5f);
    while ((bx + 1) * (bx + 2) / 2 <= t) ++bx;
    while (bx * (bx + 1) / 2 > t) --bx;
    by = t - bx * (bx + 1) / 2;
}

// epilogue + symmetric dual store (scalar chain, unchanged)
__device__ __forceinline__ void dist_store(float acc[8][8],
                                           const float* __restrict__ x2v,
                                           float* __restrict__ D,
                                           int i0, int j0, int tx, int ty,
                                           bool offdiag) {
    float res[8][8];
#pragma unroll
    for (int u = 0; u < 8; ++u) {
        int i = i0 + ty * 8 + u;
#pragma unroll
        for (int v = 0; v < 8; ++v) {
            int j = j0 + tx * 8 + v;
            float s = __fadd_rn(x2v[i], x2v[j]);
            res[u][v] = __fsub_rn(s, __fmul_rn(2.f, acc[u][v]));
        }
    }
#pragma unroll
    for (int u = 0; u < 8; ++u) {
        int i = i0 + ty * 8 + u;
        *(float4*)&D[(size_t)i * NPTS + j0 + tx * 8]     = *(float4*)&res[u][0];
        *(float4*)&D[(size_t)i * NPTS + j0 + tx * 8 + 4] = *(float4*)&res[u][4];
    }
    if (offdiag) {
#pragma unroll
        for (int v = 0; v < 8; ++v) {
            int j = j0 + tx * 8 + v;
            float4 p0 = make_float4(res[0][v], res[1][v], res[2][v], res[3][v]);
            float4 p1 = make_float4(res[4][v], res[5][v], res[6][v], res[7][v]);
            *(float4*)&D[(size_t)j * NPTS + i0 + ty * 8]     = p0;
            *(float4*)&D[(size_t)j * NPTS + i0 + ty * 8 + 4] = p1;
        }
    }
}

// ------------------------- fused kNN for C=3 (no D matrix) ------------------
// 4x unrolled scan: loads for 4 consecutive 32-candidate groups issued
// upfront (MLP=4); ballot phases still run in original ascending-j order.
__global__ __launch_bounds__(1024, 1) void knn3_kernel(
    const float* __restrict__ X,
    const float* __restrict__ x2v,
    int* __restrict__ out) {
    extern __shared__ float sm[];
    float* A0 = sm;
    float* A1 = sm + NPTS;
    float* A2 = sm + 2 * NPTS;
    float* X2 = sm + 3 * NPTS;
    float* sd = X2 + NPTS;                     // [32][KNN]
    int*   si = (int*)(sd + 32 * KNN);         // [32][KNN]

    const int tid = threadIdx.x;
    for (int j = tid; j < NPTS; j += 1024) {
        const float* p = X + (size_t)j * 3;
        A0[j] = p[0]; A1[j] = p[1]; A2[j] = p[2];
        X2[j] = x2v[j];
    }
    __syncthreads();

    const int lane = tid & 31;
    const int w    = tid >> 5;                 // 32 warps
    const int row  = blockIdx.x * 32 + w;

    const float a0 = A0[row], a1 = A1[row], a2 = A2[row];
    const float xi = X2[row];

    float* wd = sd + w * KNN;
    int*   wi = si + w * KNN;
    if (lane < KNN) { wd[lane] = FLT_MAX; wi[lane] = 0x7fffffff; }
    __syncwarp();

    float thresh = FLT_MAX;
    for (int base = 0; base < NPTS; base += 128) {
        float dv[4];
#pragma unroll
        for (int q = 0; q < 4; ++q) {
            const int j = base + q * 32 + lane;
            float acc = fmaf(a0, A0[j], 0.f);
            acc = fmaf(a1, A1[j], acc);
            acc = fmaf(a2, A2[j], acc);
            dv[q] = __fsub_rn(__fadd_rn(xi, X2[j]), __fmul_rn(2.f, acc));
        }
#pragma unroll
        for (int q = 0; q < 4; ++q) {
            float d = dv[q];
            unsigned m = __ballot_sync(0xffffffffu, d < thresh);
            while (m) {
                int src = __ffs(m) - 1;
                m &= m - 1;
                float dc = __shfl_sync(0xffffffffu, d, src);
                int   jc = base + q * 32 + src;
                if (lane == 0) {
                    if (dc < wd[KNN - 1]) {
                        int p = KNN - 1;
                        while (p > 0 && wd[p - 1] > dc) {
                            wd[p] = wd[p - 1];
                            wi[p] = wi[p - 1];
                            --p;
                        }
                        wd[p] = dc;
                        wi[p] = jc;
                    }
                }
                __syncwarp();
                thresh = wd[KNN - 1];
            }
        }
    }
    if (lane < KNN) out[row * KNN + lane] = wi[lane];
}

// ------------------------- symmetric pairwise distance (FFMA2 mainloop) -----
__global__ __launch_bounds__(256, 2) void dist_sym_kernel(
    const float* __restrict__ X, int ld,
    const float* __restrict__ x2v,
    float* __restrict__ D, int K) {
    __shared__ float As[2][BK][BM + 4];
    __shared__ float Bs[2][BK][BN + 4];

    int bx, by;
    tri_decode(blockIdx.x, bx, by);
    const int i0 = bx * BM, j0 = by * BN;
    const int tid = threadIdx.x;
    const int tx = tid & 15, ty = tid >> 4;

    unsigned long long acc2[8][4];
#pragma unroll
    for (int u = 0; u < 8; ++u)
#pragma unroll
        for (int p = 0; p < 4; ++p) acc2[u][p] = 0ull;   // {+0f,+0f}

#pragma unroll
    for (int p = 0; p < 8; ++p) {
        int e = tid + 256 * p, r = e >> 4, c = e & 15;
        As[0][c][r] = (c < K) ? X[(size_t)(i0 + r) * ld + c] : 0.f;
        Bs[0][c][r] = (c < K) ? X[(size_t)(j0 + r) * ld + c] : 0.f;
    }
    __syncthreads();

    const int nt = (K + BK - 1) / BK;
    int buf = 0;
    for (int t = 1; t < nt; ++t) {
        const int kk = t * BK;
        float pa[8], pb[8];
#pragma unroll
        for (int p = 0; p < 8; ++p) {
            int e = tid + 256 * p, r = e >> 4, c = e & 15;
            pa[p] = (kk + c < K) ? X[(size_t)(i0 + r) * ld + kk + c] : 0.f;
            pb[p] = (kk + c < K) ? X[(size_t)(j0 + r) * ld + kk + c] : 0.f;
        }
#pragma unroll
        for (int k = 0; k < BK; ++k) {
            float a[8];
            *(float4*)&a[0] = *(const float4*)&As[buf][k][ty * 8];
            *(float4*)&a[4] = *(const float4*)&As[buf][k][ty * 8 + 4];
            ulonglong2 t0 = *(const ulonglong2*)&Bs[buf][k][tx * 8];
            ulonglong2 t1 = *(const ulonglong2*)&Bs[buf][k][tx * 8 + 4];
            unsigned long long b2[4] = {t0.x, t0.y, t1.x, t1.y};
#pragma unroll
            for (int u = 0; u < 8; ++u) {
                unsigned long long a2 = pack2(a[u]);
#pragma unroll
                for (int p = 0; p < 4; ++p)
                    acc2[u][p] = ffma2(a2, b2[p], acc2[u][p]);
            }
        }
#pragma unroll
        for (int p = 0; p < 8; ++p) {
            int e = tid + 256 * p, r = e >> 4, c = e & 15;
            As[buf ^ 1][c][r] = pa[p];
            Bs[buf ^ 1][c][r] = pb[p];
        }
        __syncthreads();
        buf ^= 1;
    }
#pragma unroll
    for (int k = 0; k < BK; ++k) {
        float a[8];
        *(float4*)&a[0] = *(const float4*)&As[buf][k][ty * 8];
        *(float4*)&a[4] = *(const float4*)&As[buf][k][ty * 8 + 4];
        ulonglong2 t0 = *(const ulonglong2*)&Bs[buf][k][tx * 8];
        ulonglong2 t1 = *(const ulonglong2*)&Bs[buf][k][tx * 8 + 4];
        unsigned long long b2[4] = {t0.x, t0.y, t1.x, t1.y};
#pragma unroll
        for (int u = 0; u < 8; ++u) {
            unsigned long long a2 = pack2(a[u]);
#pragma unroll
            for (int p = 0; p < 4; ++p)
                acc2[u][p] = ffma2(a2, b2[p], acc2[u][p]);
        }
    }

    float acc[8][8];
#pragma unroll
    for (int u = 0; u < 8; ++u)
#pragma unroll
        for (int p = 0; p < 4; ++p)
            unpack2(acc2[u][p], acc[u][2 * p], acc[u][2 * p + 1]);

    dist_store(acc, x2v, D, i0, j0, tx, ty, bx != by);
}

// ------------------------- tiled fp32 GEMM (MLP, FFMA2 mainloop) ------------
__global__ __launch_bounds__(256, 2) void gemm_kernel(
    const float* __restrict__ A, int lda,
    const float* __restrict__ B, int ldb,
    const float* __restrict__ bias,
    float* __restrict__ Cout, int ldc,
    int N, int K) {
    __shared__ float As[2][BK][BM + 4];
    __shared__ float Bs[2][BK][BN + 4];

    const int tid = threadIdx.x;
    const int tx = tid & 15, ty = tid >> 4;
    const int i0 = blockIdx.y * BM;
    const int j0 = blockIdx.x * BN;

    unsigned long long acc2[8][4];
#pragma unroll
    for (int u = 0; u < 8; ++u)
#pragma unroll
        for (int p = 0; p < 4; ++p) acc2[u][p] = 0ull;

#pragma unroll
    for (int p = 0; p < 8; ++p) {
        int e = tid + 256 * p;
        {
            int r = e >> 4, c = e & 15;
            As[0][c][r] = (c < K) ? A[(size_t)(i0 + r) * lda + c] : 0.f;
        }
        {
            int r = e >> 7, c = e & 127;
            Bs[0][r][c] = (r < K && j0 + c < N)
                              ? B[(size_t)r * ldb + j0 + c] : 0.f;
        }
    }
    __syncthreads();

    const int nt = (K + BK - 1) / BK;
    int buf = 0;
    for (int t = 1; t < nt; ++t) {
        const int kk = t * BK;
        float pa[8], pb[8];
#pragma unroll
        for (int p = 0; p < 8; ++p) {
            int e = tid + 256 * p;
            {
                int r = e >> 4, c = e & 15;
                pa[p] = (kk + c < K) ? A[(size_t)(i0 + r) * lda + kk + c] : 0.f;
            }
            {
                int r = e >> 7, c = e & 127;
                pb[p] = (kk + r < K && j0 + c < N)
                            ? B[(size_t)(kk + r) * ldb + j0 + c] : 0.f;
            }
        }
#pragma unroll
        for (int k = 0; k < BK; ++k) {
            float a[8];
            *(float4*)&a[0] = *(const float4*)&As[buf][k][ty * 8];
            *(float4*)&a[4] = *(const float4*)&As[buf][k][ty * 8 + 4];
            ulonglong2 t0 = *(const ulonglong2*)&Bs[buf][k][tx * 8];
            ulonglong2 t1 = *(const ulonglong2*)&Bs[buf][k][tx * 8 + 4];
            unsigned long long b2[4] = {t0.x, t0.y, t1.x, t1.y};
#pragma unroll
            for (int u = 0; u < 8; ++u) {
                unsigned long long a2 = pack2(a[u]);
#pragma unroll
                for (int p = 0; p < 4; ++p)
                    acc2[u][p] = ffma2(a2, b2[p], acc2[u][p]);
            }
        }
#pragma unroll
        for (int p = 0; p < 8; ++p) {
            int e = tid + 256 * p;
            { int r = e >> 4, c = e & 15;  As[buf ^ 1][c][r] = pa[p]; }
            { int r = e >> 7, c = e & 127; Bs[buf ^ 1][r][c] = pb[p]; }
        }
        __syncthreads();
        buf ^= 1;
    }
#pragma unroll
    for (int k = 0; k < BK; ++k) {
        float a[8];
        *(float4*)&a[0] = *(const float4*)&As[buf][k][ty * 8];
        *(float4*)&a[4] = *(const float4*)&As[buf][k][ty * 8 + 4];
        ulonglong2 t0 = *(const ulonglong2*)&Bs[buf][k][tx * 8];
        ulonglong2 t1 = *(const ulonglong2*)&Bs[buf][k][tx * 8 + 4];
        unsigned long long b2[4] = {t0.x, t0.y, t1.x, t1.y};
#pragma unroll
        for (int u = 0; u < 8; ++u) {
            unsigned long long a2 = pack2(a[u]);
#pragma unroll
            for (int p = 0; p < 4; ++p)
                acc2[u][p] = ffma2(a2, b2[p], acc2[u][p]);
        }
    }

    float acc[8][8];
#pragma unroll
    for (int u = 0; u < 8; ++u)
#pragma unroll
        for (int p = 0; p < 4; ++p)
            unpack2(acc2[u][p], acc[u][2 * p], acc[u][2 * p + 1]);

#pragma unroll
    for (int u = 0; u < 8; ++u) {
        int i = i0 + ty * 8 + u;
#pragma unroll
        for (int v = 0; v < 8; ++v) {
            int j = j0 + tx * 8 + v;
            if (j < N)
                Cout[(size_t)i * ldc + j] =
                    fmaxf(__fadd_rn(acc[u][v], bias[j]), 0.f);
        }
    }
}

// ------------------------- top-20 selection (warp per row, 4x unrolled) -----
__global__ void topk_kernel(const float* __restrict__ D, int* __restrict__ out) {
    __shared__ float sd[8][KNN];
    __shared__ int   si[8][KNN];

    const int lane = threadIdx.x & 31;
    const int wloc = threadIdx.x >> 5;
    const int row  = (blockIdx.x * blockDim.x + threadIdx.x) >> 5;

    if (lane < KNN) { sd[wloc][lane] = FLT_MAX; si[wloc][lane] = 0x7fffffff; }
    __syncwarp();

    const float* r = D + (size_t)row * NPTS;
    float* wd = sd[wloc];
    int*   wi = si[wloc];
    float thresh = FLT_MAX;

    for (int base = 0; base < NPTS; base += 128) {
        float dv[4];
        dv[0] = r[base + lane];
        dv[1] = r[base + 32 + lane];
        dv[2] = r[base + 64 + lane];
        dv[3] = r[base + 96 + lane];
#pragma unroll
        for (int q = 0; q < 4; ++q) {
            float d = dv[q];
            unsigned m = __ballot_sync(0xffffffffu, d < thresh);
            while (m) {
                int src = __ffs(m) - 1;
                m &= m - 1;
                float dc = __shfl_sync(0xffffffffu, d, src);
                int   jc = base + q * 32 + src;
                if (lane == 0) {
                    if (dc < wd[KNN - 1]) {
                        int p = KNN - 1;
                        while (p > 0 && wd[p - 1] > dc) {
                            wd[p] = wd[p - 1];
                            wi[p] = wi[p - 1];
                            --p;
                        }
                        wd[p] = dc;
                        wi[p] = jc;
                    }
                }
                __syncwarp();
                thresh = wd[KNN - 1];
            }
        }
    }
    if (lane < KNN) out[row * KNN + lane] = wi[lane];
}

// ------------------------- erosion EdgeConv (+ fused next-layer x2) ---------
// out[i, f*C + c] = min_k ( Xin[idx[i,k], c] - w[f,k,c] ).
// If x2out != nullptr, warp 0 then computes the next layer's squared norm
// over the freshly produced C2 = F*C values with the EXACT warp-tree recipe
// (lane-strided seq mul/add from smem copies, shuffle-down tree 16,8,4,2,1)
// -- inputs bitwise equal to the gmem values the old sqnorm_warp read.
__global__ void erode_kernel(const float* __restrict__ Xin, int ldin,
                             const int* __restrict__ idx,
                             const float* __restrict__ w,
                             float* __restrict__ out, int ldout,
                             int F, int C,
                             float* __restrict__ x2out) {
    __shared__ float nb[KNN * 120];    // max C = 120
    __shared__ float ov[240];          // max F*C = 240
    const int i = blockIdx.x;
    const int* ip = idx + i * KNN;

    for (int e = threadIdx.x; e < KNN * C; e += blockDim.x) {
        int k = e / C, c = e - k * C;
        nb[e] = Xin[(size_t)ip[k] * ldin + c];
    }
    __syncthreads();

    const int FC = F * C;
    for (int e = threadIdx.x; e < FC; e += blockDim.x) {
        int f = e / C, c = e - f * C;
        float mn = FLT_MAX;
        const float* wf = w + (size_t)f * KNN * C + c;
#pragma unroll 4
        for (int k = 0; k < KNN; ++k)
            mn = fminf(mn, __fsub_rn(nb[k * C + c], wf[k * C]));
        out[(size_t)i * ldout + e] = mn;
        ov[e] = mn;
    }

    if (x2out) {
        __syncthreads();
        if (threadIdx.x < 32) {
            const int lane = threadIdx.x;
            float s = 0.f;
            for (int c = lane; c < FC; c += 32)
                s = __fadd_rn(s, __fmul_rn(ov[c], ov[c]));
#pragma unroll
            for (int off = 16; off > 0; off >>= 1)
                s = __fadd_rn(s, __shfl_down_sync(0xffffffffu, s, off));
            if (lane == 0) x2out[i] = s;
        }
    }
}

// ------------------------- final linear + log_softmax -----------------------
__global__ void head_kernel(const float* __restrict__ H,
                            const float* __restrict__ wo,
                            const float* __restrict__ bo,
                            float* __restrict__ out) {
    __shared__ float h[128];
    __shared__ float lg[40];
    __shared__ float s_lse;
    const int i = blockIdx.x;
    const int t = threadIdx.x;              // 128 threads

    h[t] = H[(size_t)i * 128 + t];
    __syncthreads();

    if (t < 40) {
        float s = 0.f;
#pragma unroll 8
        for (int k = 0; k < 128; ++k) s = fmaf(h[k], wo[k * 40 + t], s);
        lg[t] = __fadd_rn(s, bo[t]);
    }
    __syncthreads();

    if (t == 0) {
        float m = -FLT_MAX;
        for (int n = 0; n < 40; ++n) m = fmaxf(m, lg[n]);
        float s = 0.f;
        for (int n = 0; n < 40; ++n) s = __fadd_rn(s, expf(__fsub_rn(lg[n], m)));
        s_lse = __fadd_rn(m, logf(s));
    }
    __syncthreads();

    if (t < 40) out[(size_t)i * 40 + t] = __fsub_rn(lg[t], s_lse);
}

// ------------------------- launch sequence ----------------------------------
extern "C" void kernel_launch(void* const* d_in, const int* in_sizes, int n_in,
                              void* d_out, int out_size) {
    const float* x      = (const float*)d_in[0];
    const float* w1     = (const float*)d_in[1];
    const float* w2     = (const float*)d_in[2];
    const float* w3     = (const float*)d_in[3];
    const float* lin1_w = (const float*)d_in[4];
    const float* lin1_b = (const float*)d_in[5];
    const float* wa     = (const float*)d_in[6];
    const float* ba     = (const float*)d_in[7];
    const float* wb     = (const float*)d_in[8];
    const float* bb     = (const float*)d_in[9];
    const float* wo     = (const float*)d_in[10];
    const float* bo     = (const float*)d_in[11];
    float* out = (float*)d_out;

    float *D, *x2, *cat, *h1, *h2, *h3;
    int* idxp;
    cudaGetSymbolAddress((void**)&D,   g_D);
    cudaGetSymbolAddress((void**)&x2,  g_x2);
    cudaGetSymbolAddress((void**)&idxp,g_idx);
    cudaGetSymbolAddress((void**)&cat, g_cat);
    cudaGetSymbolAddress((void**)&h1,  g_h1);
    cudaGetSymbolAddress((void**)&h2,  g_h2);
    cudaGetSymbolAddress((void**)&h3,  g_h3);

    const int NB = NPTS / BM;                 // 64 tiles per dim
    const int NTRI = NB * (NB + 1) / 2;       // 2080 lower-triangle blocks

    const int smem_knn3 = (4 * NPTS + 32 * KNN) * (int)sizeof(float)
                        + 32 * KNN * (int)sizeof(int);   // ~133 KB
    cudaFuncSetAttribute(knn3_kernel,
                         cudaFuncAttributeMaxDynamicSharedMemorySize, smem_knn3);

    // ---- layer 1: kNN on x (C=3) fused, erode (+x2 for layer 2)
    sqnorm_seq_kernel<<<32, 256>>>(x, 3, 3, x2);
    knn3_kernel<<<NPTS / 32, 1024, smem_knn3>>>(x, x2, idxp);
    erode_kernel<<<NPTS, 128>>>(x, 3, idxp, w1, cat, 420, 20, 3, x2);

    // ---- layer 2: kNN on x1 (C=60), erode (+x2 for layer 3)
    dist_sym_kernel<<<NTRI, 256>>>(cat, 420, x2, D, 60);
    topk_kernel<<<NPTS / 8, 256>>>(D, idxp);
    erode_kernel<<<NPTS, 128>>>(cat, 420, idxp, w2, cat + 60, 420, 2, 60, x2);

    // ---- layer 3: kNN on x2 (C=120), erode
    dist_sym_kernel<<<NTRI, 256>>>(cat + 60, 420, x2, D, 120);
    topk_kernel<<<NPTS / 8, 256>>>(D, idxp);
    erode_kernel<<<NPTS, 128>>>(cat + 60, 420, idxp, w3, cat + 180, 420, 2, 120,
                                nullptr);

    // ---- MLP head
    gemm_kernel<<<dim3(1024 / BN, NPTS / BM), 256>>>(
        cat, 420, lin1_w, 1024, lin1_b, h1, 1024, 1024, 420);
    gemm_kernel<<<dim3(2, NPTS / BM), 256>>>(
        h1, 1024, wa, 256, ba, h2, 256, 256, 1024);
    gemm_kernel<<<dim3(1, NPTS / BM), 256>>>(
        h2, 256, wb, 128, bb, h3, 128, 128, 256);

    head_kernel<<<NPTS, 128>>>(h3, wo, bo, out);
}

// round 15
// speedup vs baseline: 1.2170x; 1.0112x over previous
#include <cuda_runtime.h>
#include <math.h>
#include <float.h>

#define NPTS 8192
#define KNN  20

// ------------------------- scratch (__device__ globals, no allocation) ------
__device__ float g_D[(size_t)NPTS * NPTS];   // 256 MB dist matrix
__device__ float g_x2[NPTS];
__device__ int   g_idx[NPTS * KNN];
__device__ float g_cat[NPTS * 420];          // x1|x2|x3 concatenated (60|120|240)
__device__ float g_h1[NPTS * 1024];
__device__ float g_h2[NPTS * 256];
__device__ float g_h3[NPTS * 128];

// ------------------------- packed f32x2 FMA ---------------------------------
__device__ __forceinline__ unsigned long long ffma2(
    unsigned long long a, unsigned long long b, unsigned long long c) {
    unsigned long long d;
    asm("fma.rn.f32x2 %0, %1, %2, %3;" : "=l"(d) : "l"(a), "l"(b), "l"(c));
    return d;
}
__device__ __forceinline__ unsigned long long pack2(float x) {
    unsigned long long d;
    asm("mov.b64 %0, {%1, %2};" : "=l"(d) : "f"(x), "f"(x));
    return d;
}
__device__ __forceinline__ void unpack2(unsigned long long p, float& lo, float& hi) {
    asm("mov.b64 {%0, %1}, %2;" : "=f"(lo), "=f"(hi) : "l"(p));
}

// ------------------------- squared norms (layer 1 only) ---------------------
__global__ void sqnorm_seq_kernel(const float* __restrict__ X, int ld, int C,
                                  float* __restrict__ x2) {
    int i = blockIdx.x * blockDim.x + threadIdx.x;
    if (i >= NPTS) return;
    const float* r = X + (size_t)i * ld;
    float s = 0.f;
    for (int c = 0; c < C; ++c)
        s = __fadd_rn(s, __fmul_rn(r[c], r[c]));
    x2[i] = s;
}

#define BM 128
#define BN 128

// triangle decode: linear block id -> (bx, by), by <= bx
__device__ __forceinline__ void tri_decode(int t, int& bx, int& by) {
    bx = (int)((sqrtf(8.f * (float)t + 1.f) - 1.f) * 0.5f);
    while ((bx + 1) * (bx + 2) / 2 <= t) ++bx;
    while (bx * (bx + 1) / 2 > t) --bx;
    by = t - bx * (bx + 1) / 2;
}

// epilogue + symmetric dual store (scalar chain, unchanged)
__device__ __forceinline__ void dist_store(float acc[8][8],
                                           const float* __restrict__ x2v,
                                           float* __restrict__ D,
                                           int i0, int j0, int tx, int ty,
                                           bool offdiag) {
    float res[8][8];
#pragma unroll
    for (int u = 0; u < 8; ++u) {
        int i = i0 + ty * 8 + u;
#pragma unroll
        for (int v = 0; v < 8; ++v) {
            int j = j0 + tx * 8 + v;
            float s = __fadd_rn(x2v[i], x2v[j]);
            res[u][v] = __fsub_rn(s, __fmul_rn(2.f, acc[u][v]));
        }
    }
#pragma unroll
    for (int u = 0; u < 8; ++u) {
        int i = i0 + ty * 8 + u;
        *(float4*)&D[(size_t)i * NPTS + j0 + tx * 8]     = *(float4*)&res[u][0];
        *(float4*)&D[(size_t)i * NPTS + j0 + tx * 8 + 4] = *(float4*)&res[u][4];
    }
    if (offdiag) {
#pragma unroll
        for (int v = 0; v < 8; ++v) {
            int j = j0 + tx * 8 + v;
            float4 p0 = make_float4(res[0][v], res[1][v], res[2][v], res[3][v]);
            float4 p1 = make_float4(res[4][v], res[5][v], res[6][v], res[7][v]);
            *(float4*)&D[(size_t)j * NPTS + i0 + ty * 8]     = p0;
            *(float4*)&D[(size_t)j * NPTS + i0 + ty * 8 + 4] = p1;
        }
    }
}

// ------------------------- fused kNN for C=3 (no D matrix) ------------------
__global__ __launch_bounds__(1024, 1) void knn3_kernel(
    const float* __restrict__ X,
    const float* __restrict__ x2v,
    int* __restrict__ out) {
    extern __shared__ float sm[];
    float* A0 = sm;
    float* A1 = sm + NPTS;
    float* A2 = sm + 2 * NPTS;
    float* X2 = sm + 3 * NPTS;
    float* sd = X2 + NPTS;                     // [32][KNN]
    int*   si = (int*)(sd + 32 * KNN);         // [32][KNN]

    const int tid = threadIdx.x;
    for (int j = tid; j < NPTS; j += 1024) {
        const float* p = X + (size_t)j * 3;
        A0[j] = p[0]; A1[j] = p[1]; A2[j] = p[2];
        X2[j] = x2v[j];
    }
    __syncthreads();

    const int lane = tid & 31;
    const int w    = tid >> 5;
    const int row  = blockIdx.x * 32 + w;

    const float a0 = A0[row], a1 = A1[row], a2 = A2[row];
    const float xi = X2[row];

    float* wd = sd + w * KNN;
    int*   wi = si + w * KNN;
    if (lane < KNN) { wd[lane] = FLT_MAX; wi[lane] = 0x7fffffff; }
    __syncwarp();

    float thresh = FLT_MAX;
    for (int base = 0; base < NPTS; base += 128) {
        float dv[4];
#pragma unroll
        for (int q = 0; q < 4; ++q) {
            const int j = base + q * 32 + lane;
            float acc = fmaf(a0, A0[j], 0.f);
            acc = fmaf(a1, A1[j], acc);
            acc = fmaf(a2, A2[j], acc);
            dv[q] = __fsub_rn(__fadd_rn(xi, X2[j]), __fmul_rn(2.f, acc));
        }
#pragma unroll
        for (int q = 0; q < 4; ++q) {
            float d = dv[q];
            unsigned m = __ballot_sync(0xffffffffu, d < thresh);
            while (m) {
                int src = __ffs(m) - 1;
                m &= m - 1;
                float dc = __shfl_sync(0xffffffffu, d, src);
                int   jc = base + q * 32 + src;
                if (lane == 0) {
                    if (dc < wd[KNN - 1]) {
                        int p = KNN - 1;
                        while (p > 0 && wd[p - 1] > dc) {
                            wd[p] = wd[p - 1];
                            wi[p] = wi[p - 1];
                            --p;
                        }
                        wd[p] = dc;
                        wi[p] = jc;
                    }
                }
                __syncwarp();
                thresh = wd[KNN - 1];
            }
        }
    }
    if (lane < KNN) out[row * KNN + lane] = wi[lane];
}

// ------------------------- symmetric pairwise distance ----------------------
// BK=20 divides K=60/120 exactly: no zero-pad k-steps, fewer barriers.
// Ascending-k single-accumulator FFMA chain preserved (bitwise identical:
// removed steps were fma(0,0,acc) no-ops).
template <int K>
__global__ __launch_bounds__(256, 2) void dist_sym_kernel(
    const float* __restrict__ X, int ld,
    const float* __restrict__ x2v,
    float* __restrict__ D) {
    const int BKT = 20;
    __shared__ float As[2][BKT][BM + 4];
    __shared__ float Bs[2][BKT][BN + 4];

    int bx, by;
    tri_decode(blockIdx.x, bx, by);
    const int i0 = bx * BM, j0 = by * BN;
    const int tid = threadIdx.x;
    const int tx = tid & 15, ty = tid >> 4;

    unsigned long long acc2[8][4];
#pragma unroll
    for (int u = 0; u < 8; ++u)
#pragma unroll
        for (int p = 0; p < 4; ++p) acc2[u][p] = 0ull;

    // prologue: tile 0   (BM*BKT = 2560 elems, 10 per thread)
#pragma unroll
    for (int p = 0; p < 10; ++p) {
        int e = tid + 256 * p, r = e / BKT, c = e - r * BKT;
        As[0][c][r] = X[(size_t)(i0 + r) * ld + c];
        Bs[0][c][r] = X[(size_t)(j0 + r) * ld + c];
    }
    __syncthreads();

    const int nt = K / BKT;
    int buf = 0;
    for (int t = 1; t < nt; ++t) {
        const int kk = t * BKT;
        float pa[10], pb[10];
#pragma unroll
        for (int p = 0; p < 10; ++p) {
            int e = tid + 256 * p, r = e / BKT, c = e - r * BKT;
            pa[p] = X[(size_t)(i0 + r) * ld + kk + c];
            pb[p] = X[(size_t)(j0 + r) * ld + kk + c];
        }
#pragma unroll
        for (int k = 0; k < BKT; ++k) {
            float a[8];
            *(float4*)&a[0] = *(const float4*)&As[buf][k][ty * 8];
            *(float4*)&a[4] = *(const float4*)&As[buf][k][ty * 8 + 4];
            ulonglong2 t0 = *(const ulonglong2*)&Bs[buf][k][tx * 8];
            ulonglong2 t1 = *(const ulonglong2*)&Bs[buf][k][tx * 8 + 4];
            unsigned long long b2[4] = {t0.x, t0.y, t1.x, t1.y};
#pragma unroll
            for (int u = 0; u < 8; ++u) {
                unsigned long long a2 = pack2(a[u]);
#pragma unroll
                for (int p = 0; p < 4; ++p)
                    acc2[u][p] = ffma2(a2, b2[p], acc2[u][p]);
            }
        }
#pragma unroll
        for (int p = 0; p < 10; ++p) {
            int e = tid + 256 * p, r = e / BKT, c = e - r * BKT;
            As[buf ^ 1][c][r] = pa[p];
            Bs[buf ^ 1][c][r] = pb[p];
        }
        __syncthreads();
        buf ^= 1;
    }
#pragma unroll
    for (int k = 0; k < BKT; ++k) {
        float a[8];
        *(float4*)&a[0] = *(const float4*)&As[buf][k][ty * 8];
        *(float4*)&a[4] = *(const float4*)&As[buf][k][ty * 8 + 4];
        ulonglong2 t0 = *(const ulonglong2*)&Bs[buf][k][tx * 8];
        ulonglong2 t1 = *(const ulonglong2*)&Bs[buf][k][tx * 8 + 4];
        unsigned long long b2[4] = {t0.x, t0.y, t1.x, t1.y};
#pragma unroll
        for (int u = 0; u < 8; ++u) {
            unsigned long long a2 = pack2(a[u]);
#pragma unroll
            for (int p = 0; p < 4; ++p)
                acc2[u][p] = ffma2(a2, b2[p], acc2[u][p]);
        }
    }

    float acc[8][8];
#pragma unroll
    for (int u = 0; u < 8; ++u)
#pragma unroll
        for (int p = 0; p < 4; ++p)
            unpack2(acc2[u][p], acc[u][2 * p], acc[u][2 * p + 1]);

    dist_store(acc, x2v, D, i0, j0, tx, ty, bx != by);
}

// ------------------------- GEMM 128x128, BK=20 (lin1: K=420 exact) ----------
__global__ __launch_bounds__(256, 2) void gemm128_kernel(
    const float* __restrict__ A, int lda,
    const float* __restrict__ B, int ldb,
    const float* __restrict__ bias,
    float* __restrict__ Cout, int ldc,
    int N, int K) {
    const int BKT = 20;
    __shared__ float As[2][BKT][BM + 4];
    __shared__ float Bs[2][BKT][BN + 4];

    const int tid = threadIdx.x;
    const int tx = tid & 15, ty = tid >> 4;
    const int i0 = blockIdx.y * BM;
    const int j0 = blockIdx.x * BN;

    unsigned long long acc2[8][4];
#pragma unroll
    for (int u = 0; u < 8; ++u)
#pragma unroll
        for (int p = 0; p < 4; ++p) acc2[u][p] = 0ull;

    // prologue (A: 2560 elems; B: BKT*BN = 2560 elems; 10 each per thread)
#pragma unroll
    for (int p = 0; p < 10; ++p) {
        int e = tid + 256 * p;
        { int r = e / BKT, c = e - r * BKT;
          As[0][c][r] = A[(size_t)(i0 + r) * lda + c]; }
        { int r = e >> 7, c = e & 127;
          Bs[0][r][c] = B[(size_t)r * ldb + j0 + c]; }
    }
    __syncthreads();

    const int nt = K / BKT;      // K divisible by 20 (420)
    int buf = 0;
    for (int t = 1; t < nt; ++t) {
        const int kk = t * BKT;
        float pa[10], pb[10];
#pragma unroll
        for (int p = 0; p < 10; ++p) {
            int e = tid + 256 * p;
            { int r = e / BKT, c = e - r * BKT;
              pa[p] = A[(size_t)(i0 + r) * lda + kk + c]; }
            { int r = e >> 7, c = e & 127;
              pb[p] = B[(size_t)(kk + r) * ldb + j0 + c]; }
        }
#pragma unroll
        for (int k = 0; k < BKT; ++k) {
            float a[8];
            *(float4*)&a[0] = *(const float4*)&As[buf][k][ty * 8];
            *(float4*)&a[4] = *(const float4*)&As[buf][k][ty * 8 + 4];
            ulonglong2 t0 = *(const ulonglong2*)&Bs[buf][k][tx * 8];
            ulonglong2 t1 = *(const ulonglong2*)&Bs[buf][k][tx * 8 + 4];
            unsigned long long b2[4] = {t0.x, t0.y, t1.x, t1.y};
#pragma unroll
            for (int u = 0; u < 8; ++u) {
                unsigned long long a2 = pack2(a[u]);
#pragma unroll
                for (int p = 0; p < 4; ++p)
                    acc2[u][p] = ffma2(a2, b2[p], acc2[u][p]);
            }
        }
#pragma unroll
        for (int p = 0; p < 10; ++p) {
            int e = tid + 256 * p;
            { int r = e / BKT, c = e - r * BKT; As[buf ^ 1][c][r] = pa[p]; }
            { int r = e >> 7, c = e & 127;      Bs[buf ^ 1][r][c] = pb[p]; }
        }
        __syncthreads();
        buf ^= 1;
    }
#pragma unroll
    for (int k = 0; k < BKT; ++k) {
        float a[8];
        *(float4*)&a[0] = *(const float4*)&As[buf][k][ty * 8];
        *(float4*)&a[4] = *(const float4*)&As[buf][k][ty * 8 + 4];
        ulonglong2 t0 = *(const ulonglong2*)&Bs[buf][k][tx * 8];
        ulonglong2 t1 = *(const ulonglong2*)&Bs[buf][k][tx * 8 + 4];
        unsigned long long b2[4] = {t0.x, t0.y, t1.x, t1.y};
#pragma unroll
        for (int u = 0; u < 8; ++u) {
            unsigned long long a2 = pack2(a[u]);
#pragma unroll
            for (int p = 0; p < 4; ++p)
                acc2[u][p] = ffma2(a2, b2[p], acc2[u][p]);
        }
    }

    float acc[8][8];
#pragma unroll
    for (int u = 0; u < 8; ++u)
#pragma unroll
        for (int p = 0; p < 4; ++p)
            unpack2(acc2[u][p], acc[u][2 * p], acc[u][2 * p + 1]);

#pragma unroll
    for (int u = 0; u < 8; ++u) {
        int i = i0 + ty * 8 + u;
#pragma unroll
        for (int v = 0; v < 8; ++v)
            Cout[(size_t)i * ldc + j0 + tx * 8 + v] =
                fmaxf(__fadd_rn(acc[u][v], bias[j0 + tx * 8 + v]), 0.f);
    }
}

// ------------------------- GEMM 64x128, BK=16 (wa, wb: more blocks) ---------
// BM=64 doubles the grid for the small-N layers; ~80 regs -> 3 CTAs/SM.
__global__ __launch_bounds__(256, 3) void gemm64_kernel(
    const float* __restrict__ A, int lda,
    const float* __restrict__ B, int ldb,
    const float* __restrict__ bias,
    float* __restrict__ Cout, int ldc,
    int N, int K) {
    const int BKT = 16;
    __shared__ float As[2][BKT][64 + 4];
    __shared__ float Bs[2][BKT][128 + 4];

    const int tid = threadIdx.x;
    const int tx = tid & 15, ty = tid >> 4;      // ty: 4-row groups
    const int i0 = blockIdx.y * 64;
    const int j0 = blockIdx.x * 128;

    unsigned long long acc2[4][4];
#pragma unroll
    for (int u = 0; u < 4; ++u)
#pragma unroll
        for (int p = 0; p < 4; ++p) acc2[u][p] = 0ull;

    // prologue (A: 64*16=1024 elems -> 4/thread; B: 16*128=2048 -> 8/thread)
#pragma unroll
    for (int p = 0; p < 4; ++p) {
        int e = tid + 256 * p, r = e >> 4, c = e & 15;
        As[0][c][r] = A[(size_t)(i0 + r) * lda + c];
    }
#pragma unroll
    for (int p = 0; p < 8; ++p) {
        int e = tid + 256 * p, r = e >> 7, c = e & 127;
        Bs[0][r][c] = B[(size_t)r * ldb + j0 + c];
    }
    __syncthreads();

    const int nt = K / BKT;      // K divisible by 16 (1024, 256)
    int buf = 0;
    for (int t = 1; t < nt; ++t) {
        const int kk = t * BKT;
        float pa[4], pb[8];
#pragma unroll
        for (int p = 0; p < 4; ++p) {
            int e = tid + 256 * p, r = e >> 4, c = e & 15;
            pa[p] = A[(size_t)(i0 + r) * lda + kk + c];
        }
#pragma unroll
        for (int p = 0; p < 8; ++p) {
            int e = tid + 256 * p, r = e >> 7, c = e & 127;
            pb[p] = B[(size_t)(kk + r) * ldb + j0 + c];
        }
#pragma unroll
        for (int k = 0; k < BKT; ++k) {
            float a[4];
            *(float4*)&a[0] = *(const float4*)&As[buf][k][ty * 4];
            ulonglong2 t0 = *(const ulonglong2*)&Bs[buf][k][tx * 8];
            ulonglong2 t1 = *(const ulonglong2*)&Bs[buf][k][tx * 8 + 4];
            unsigned long long b2[4] = {t0.x, t0.y, t1.x, t1.y};
#pragma unroll
            for (int u = 0; u < 4; ++u) {
                unsigned long long a2 = pack2(a[u]);
#pragma unroll
                for (int p = 0; p < 4; ++p)
                    acc2[u][p] = ffma2(a2, b2[p], acc2[u][p]);
            }
        }
#pragma unroll
        for (int p = 0; p < 4; ++p) {
            int e = tid + 256 * p, r = e >> 4, c = e & 15;
            As[buf ^ 1][c][r] = pa[p];
        }
#pragma unroll
        for (int p = 0; p < 8; ++p) {
            int e = tid + 256 * p, r = e >> 7, c = e & 127;
            Bs[buf ^ 1][r][c] = pb[p];
        }
        __syncthreads();
        buf ^= 1;
    }
#pragma unroll
    for (int k = 0; k < BKT; ++k) {
        float a[4];
        *(float4*)&a[0] = *(const float4*)&As[buf][k][ty * 4];
        ulonglong2 t0 = *(const ulonglong2*)&Bs[buf][k][tx * 8];
        ulonglong2 t1 = *(const ulonglong2*)&Bs[buf][k][tx * 8 + 4];
        unsigned long long b2[4] = {t0.x, t0.y, t1.x, t1.y};
#pragma unroll
        for (int u = 0; u < 4; ++u) {
            unsigned long long a2 = pack2(a[u]);
#pragma unroll
            for (int p = 0; p < 4; ++p)
                acc2[u][p] = ffma2(a2, b2[p], acc2[u][p]);
        }
    }

    float acc[4][8];
#pragma unroll
    for (int u = 0; u < 4; ++u)
#pragma unroll
        for (int p = 0; p < 4; ++p)
            unpack2(acc2[u][p], acc[u][2 * p], acc[u][2 * p + 1]);

#pragma unroll
    for (int u = 0; u < 4; ++u) {
        int i = i0 + ty * 4 + u;
#pragma unroll
        for (int v = 0; v < 8; ++v) {
            int j = j0 + tx * 8 + v;
            if (j < N)
                Cout[(size_t)i * ldc + j] =
                    fmaxf(__fadd_rn(acc[u][v], bias[j]), 0.f);
        }
    }
}

// ------------------------- top-20 selection (warp per row, 4x unrolled) -----
__global__ void topk_kernel(const float* __restrict__ D, int* __restrict__ out) {
    __shared__ float sd[8][KNN];
    __shared__ int   si[8][KNN];

    const int lane = threadIdx.x & 31;
    const int wloc = threadIdx.x >> 5;
    const int row  = (blockIdx.x * blockDim.x + threadIdx.x) >> 5;

    if (lane < KNN) { sd[wloc][lane] = FLT_MAX; si[wloc][lane] = 0x7fffffff; }
    __syncwarp();

    const float* r = D + (size_t)row * NPTS;
    float* wd = sd[wloc];
    int*   wi = si[wloc];
    float thresh = FLT_MAX;

    for (int base = 0; base < NPTS; base += 128) {
        float dv[4];
        dv[0] = r[base + lane];
        dv[1] = r[base + 32 + lane];
        dv[2] = r[base + 64 + lane];
        dv[3] = r[base + 96 + lane];
#pragma unroll
        for (int q = 0; q < 4; ++q) {
            float d = dv[q];
            unsigned m = __ballot_sync(0xffffffffu, d < thresh);
            while (m) {
                int src = __ffs(m) - 1;
                m &= m - 1;
                float dc = __shfl_sync(0xffffffffu, d, src);
                int   jc = base + q * 32 + src;
                if (lane == 0) {
                    if (dc < wd[KNN - 1]) {
                        int p = KNN - 1;
                        while (p > 0 && wd[p - 1] > dc) {
                            wd[p] = wd[p - 1];
                            wi[p] = wi[p - 1];
                            --p;
                        }
                        wd[p] = dc;
                        wi[p] = jc;
                    }
                }
                __syncwarp();
                thresh = wd[KNN - 1];
            }
        }
    }
    if (lane < KNN) out[row * KNN + lane] = wi[lane];
}

// ------------------------- erosion EdgeConv (+ fused next-layer x2) ---------
__global__ void erode_kernel(const float* __restrict__ Xin, int ldin,
                             const int* __restrict__ idx,
                             const float* __restrict__ w,
                             float* __restrict__ out, int ldout,
                             int F, int C,
                             float* __restrict__ x2out) {
    __shared__ float nb[KNN * 120];    // max C = 120
    __shared__ float ov[240];          // max F*C = 240
    const int i = blockIdx.x;
    const int* ip = idx + i * KNN;

    for (int e = threadIdx.x; e < KNN * C; e += blockDim.x) {
        int k = e / C, c = e - k * C;
        nb[e] = Xin[(size_t)ip[k] * ldin + c];
    }
    __syncthreads();

    const int FC = F * C;
    for (int e = threadIdx.x; e < FC; e += blockDim.x) {
        int f = e / C, c = e - f * C;
        float mn = FLT_MAX;
        const float* wf = w + (size_t)f * KNN * C + c;
#pragma unroll 4
        for (int k = 0; k < KNN; ++k)
            mn = fminf(mn, __fsub_rn(nb[k * C + c], wf[k * C]));
        out[(size_t)i * ldout + e] = mn;
        ov[e] = mn;
    }

    if (x2out) {
        __syncthreads();
        if (threadIdx.x < 32) {
            const int lane = threadIdx.x;
            float s = 0.f;
            for (int c = lane; c < FC; c += 32)
                s = __fadd_rn(s, __fmul_rn(ov[c], ov[c]));
#pragma unroll
            for (int off = 16; off > 0; off >>= 1)
                s = __fadd_rn(s, __shfl_down_sync(0xffffffffu, s, off));
            if (lane == 0) x2out[i] = s;
        }
    }
}

// ------------------------- final linear + log_softmax -----------------------
__global__ void head_kernel(const float* __restrict__ H,
                            const float* __restrict__ wo,
                            const float* __restrict__ bo,
                            float* __restrict__ out) {
    __shared__ float h[128];
    __shared__ float lg[40];
    __shared__ float s_lse;
    const int i = blockIdx.x;
    const int t = threadIdx.x;              // 128 threads

    h[t] = H[(size_t)i * 128 + t];
    __syncthreads();

    if (t < 40) {
        float s = 0.f;
#pragma unroll 8
        for (int k = 0; k < 128; ++k) s = fmaf(h[k], wo[k * 40 + t], s);
        lg[t] = __fadd_rn(s, bo[t]);
    }
    __syncthreads();

    if (t == 0) {
        float m = -FLT_MAX;
        for (int n = 0; n < 40; ++n) m = fmaxf(m, lg[n]);
        float s = 0.f;
        for (int n = 0; n < 40; ++n) s = __fadd_rn(s, expf(__fsub_rn(lg[n], m)));
        s_lse = __fadd_rn(m, logf(s));
    }
    __syncthreads();

    if (t < 40) out[(size_t)i * 40 + t] = __fsub_rn(lg[t], s_lse);
}

// ------------------------- launch sequence ----------------------------------
extern "C" void kernel_launch(void* const* d_in, const int* in_sizes, int n_in,
                              void* d_out, int out_size) {
    const float* x      = (const float*)d_in[0];
    const float* w1     = (const float*)d_in[1];
    const float* w2     = (const float*)d_in[2];
    const float* w3     = (const float*)d_in[3];
    const float* lin1_w = (const float*)d_in[4];
    const float* lin1_b = (const float*)d_in[5];
    const float* wa     = (const float*)d_in[6];
    const float* ba     = (const float*)d_in[7];
    const float* wb     = (const float*)d_in[8];
    const float* bb     = (const float*)d_in[9];
    const float* wo     = (const float*)d_in[10];
    const float* bo     = (const float*)d_in[11];
    float* out = (float*)d_out;

    float *D, *x2, *cat, *h1, *h2, *h3;
    int* idxp;
    cudaGetSymbolAddress((void**)&D,   g_D);
    cudaGetSymbolAddress((void**)&x2,  g_x2);
    cudaGetSymbolAddress((void**)&idxp,g_idx);
    cudaGetSymbolAddress((void**)&cat, g_cat);
    cudaGetSymbolAddress((void**)&h1,  g_h1);
    cudaGetSymbolAddress((void**)&h2,  g_h2);
    cudaGetSymbolAddress((void**)&h3,  g_h3);

    const int NB = NPTS / BM;                 // 64 tiles per dim
    const int NTRI = NB * (NB + 1) / 2;       // 2080 lower-triangle blocks

    const int smem_knn3 = (4 * NPTS + 32 * KNN) * (int)sizeof(float)
                        + 32 * KNN * (int)sizeof(int);   // ~133 KB
    cudaFuncSetAttribute(knn3_kernel,
                         cudaFuncAttributeMaxDynamicSharedMemorySize, smem_knn3);

    // ---- layer 1: kNN on x (C=3) fused, erode (+x2 for layer 2)
    sqnorm_seq_kernel<<<32, 256>>>(x, 3, 3, x2);
    knn3_kernel<<<NPTS / 32, 1024, smem_knn3>>>(x, x2, idxp);
    erode_kernel<<<NPTS, 128>>>(x, 3, idxp, w1, cat, 420, 20, 3, x2);

    // ---- layer 2: kNN on x1 (C=60), erode (+x2 for layer 3)
    dist_sym_kernel<60><<<NTRI, 256>>>(cat, 420, x2, D);
    topk_kernel<<<NPTS / 8, 256>>>(D, idxp);
    erode_kernel<<<NPTS, 128>>>(cat, 420, idxp, w2, cat + 60, 420, 2, 60, x2);

    // ---- layer 3: kNN on x2 (C=120), erode
    dist_sym_kernel<120><<<NTRI, 256>>>(cat + 60, 420, x2, D);
    topk_kernel<<<NPTS / 8, 256>>>(D, idxp);
    erode_kernel<<<NPTS, 128>>>(cat + 60, 420, idxp, w3, cat + 180, 420, 2, 120,
                                nullptr);

    // ---- MLP head
    gemm128_kernel<<<dim3(1024 / BN, NPTS / BM), 256>>>(
        cat, 420, lin1_w, 1024, lin1_b, h1, 1024, 1024, 420);
    gemm64_kernel<<<dim3(2, NPTS / 64), 256>>>(
        h1, 1024, wa, 256, ba, h2, 256, 256, 1024);
    gemm64_kernel<<<dim3(1, NPTS / 64), 256>>>(
        h2, 256, wb, 128, bb, h3, 128, 128, 256);

    head_kernel<<<NPTS, 128>>>(h3, wo, bo, out);
}